// round 1
// baseline (speedup 1.0000x reference)
#include <cuda_runtime.h>
#include <cuda_bf16.h>
#include <cstddef>

// Problem constants
#define BATCH 2
#define SEQ   2048
#define EMB   1024
#define HEADS 16
#define HDIM  64
#define NTOK  (BATCH * SEQ)          // 4096
#define KDIM  (EMB * 8)              // 8192 expanded features
#define NB    7                      // spline bases per feature

// ---------------- scratch (static device globals; no allocation) ------------
__device__ float g_phi[(size_t)NTOK * KDIM];          // 134.2 MB, reused per projection
__device__ float g_W[(size_t)KDIM * EMB];             // 33.5 MB, reused per projection
__device__ float g_qkv[(size_t)3 * NTOK * EMB];       // 50.3 MB (Q,K,V projected)

// ---------------------------------------------------------------------------
// Kernel 1: expand input X[NTOK, EMB] -> phi[NTOK, EMB*8]:
//   phi[n, i*8+0]   = x
//   phi[n, i*8+1+j] = B_j(x),  j = 0..6  (cubic B-splines, grid_size=4, k=3)
// Knots: g[t] = -2.5 + 0.5*t, t = 0..10 (exact fp32 values, match reference).
// ---------------------------------------------------------------------------
__global__ __launch_bounds__(256) void phi_kernel(const float* __restrict__ X) {
    int idx = blockIdx.x * blockDim.x + threadIdx.x;   // over NTOK*EMB
    if (idx >= NTOK * EMB) return;
    float x = X[idx];

    float b[10];
#pragma unroll
    for (int t = 0; t < 10; t++) {
        float gt = -2.5f + 0.5f * (float)t;
        b[t] = (x >= gt && x < gt + 0.5f) ? 1.0f : 0.0f;
    }
#pragma unroll
    for (int p = 1; p <= 3; p++) {
#pragma unroll
        for (int t = 0; t < 10; t++) {
            if (t + p < 10) {
                float gt   = -2.5f + 0.5f * (float)t;
                float gtp  = gt + 0.5f * (float)p;        // g[t+p]
                float gtp1 = gtp + 0.5f;                  // g[t+p+1]
                float gt1  = gt + 0.5f;                   // g[t+1]
                float left  = (x - gt)   / (gtp - gt);
                float right = (gtp1 - x) / (gtp1 - gt1);
                b[t] = left * b[t] + right * b[t + 1];
            }
        }
    }
    float4* dst = (float4*)(g_phi + (size_t)idx * 8);
    dst[0] = make_float4(x,    b[0], b[1], b[2]);
    dst[1] = make_float4(b[3], b[4], b[5], b[6]);
}

// ---------------------------------------------------------------------------
// Kernel 2: build combined weight W[KDIM, EMB] (K-major rows):
//   W[i*8+0,   m] = base[m, i]
//   W[i*8+1+j, m] = spline[m, i, j] * scaler[m, i]
// ---------------------------------------------------------------------------
__global__ __launch_bounds__(256) void wprep_kernel(const float* __restrict__ base,
                                                    const float* __restrict__ spline,
                                                    const float* __restrict__ scaler) {
    int idx = blockIdx.x * blockDim.x + threadIdx.x;   // over EMB*EMB, m fast
    if (idx >= EMB * EMB) return;
    int m = idx & (EMB - 1);
    int i = idx >> 10;
    size_t mi = (size_t)m * EMB + i;
    g_W[(size_t)(i * 8) * EMB + m] = base[mi];
    float sc = scaler[mi];
    const float* sp = spline + (size_t)m * EMB * NB + (size_t)i * NB;
#pragma unroll
    for (int j = 0; j < NB; j++)
        g_W[(size_t)(i * 8 + 1 + j) * EMB + m] = sp[j] * sc;
}

// ---------------------------------------------------------------------------
// Kernel 3: C[NTOK, EMB] = phi[NTOK, KDIM] @ W[KDIM, EMB]
// Classic 128x128 tile, BK=16, 256 threads, 8x8 per thread, fp32.
// ---------------------------------------------------------------------------
__global__ __launch_bounds__(256, 2) void gemm_kan(int which) {
    __shared__ float As[16][132];
    __shared__ float Bs[16][132];
    const float* A = g_phi;
    const float* B = g_W;
    float* C = g_qkv + (size_t)which * NTOK * EMB;

    int row0 = blockIdx.y * 128;
    int col0 = blockIdx.x * 128;
    int tid = threadIdx.x;
    int tx = tid & 15, ty = tid >> 4;
    int ar = tid >> 2;                 // 0..63
    int akc = (tid & 3) << 2;          // 0,4,8,12
    int bk = tid >> 5;                 // 0..7
    int bm = (tid & 31) << 2;          // 0..124

    const float* Ap = A + (size_t)(row0 + ar) * KDIM + akc;
    const float* Bp = B + (size_t)bk * EMB + col0 + bm;

    float acc[8][8];
#pragma unroll
    for (int i = 0; i < 8; i++)
#pragma unroll
        for (int j = 0; j < 8; j++) acc[i][j] = 0.0f;

    for (int k0 = 0; k0 < KDIM; k0 += 16) {
        float4 a0 = *(const float4*)Ap;
        float4 a1 = *(const float4*)(Ap + (size_t)64 * KDIM);
        float4 b0 = *(const float4*)Bp;
        float4 b1 = *(const float4*)(Bp + 8 * EMB);
        __syncthreads();
        As[akc + 0][ar] = a0.x; As[akc + 1][ar] = a0.y;
        As[akc + 2][ar] = a0.z; As[akc + 3][ar] = a0.w;
        As[akc + 0][ar + 64] = a1.x; As[akc + 1][ar + 64] = a1.y;
        As[akc + 2][ar + 64] = a1.z; As[akc + 3][ar + 64] = a1.w;
        *(float4*)&Bs[bk][bm] = b0;
        *(float4*)&Bs[bk + 8][bm] = b1;
        __syncthreads();
#pragma unroll
        for (int kk = 0; kk < 16; kk++) {
            float a[8], b[8];
            *(float4*)&a[0] = *(const float4*)&As[kk][ty * 8];
            *(float4*)&a[4] = *(const float4*)&As[kk][ty * 8 + 4];
            *(float4*)&b[0] = *(const float4*)&Bs[kk][tx * 8];
            *(float4*)&b[4] = *(const float4*)&Bs[kk][tx * 8 + 4];
#pragma unroll
            for (int i = 0; i < 8; i++)
#pragma unroll
                for (int j = 0; j < 8; j++)
                    acc[i][j] = fmaf(a[i], b[j], acc[i][j]);
        }
        Ap += 16;
        Bp += (size_t)16 * EMB;
    }
#pragma unroll
    for (int i = 0; i < 8; i++) {
        float* cp = C + (size_t)(row0 + ty * 8 + i) * EMB + col0 + tx * 8;
        *(float4*)cp       = make_float4(acc[i][0], acc[i][1], acc[i][2], acc[i][3]);
        *(float4*)(cp + 4) = make_float4(acc[i][4], acc[i][5], acc[i][6], acc[i][7]);
    }
}

// ---------------------------------------------------------------------------
// Kernel 4: scores S[bh, q, k] = (Q_bh[q,:] . K_bh[k,:]) / 8   (NT GEMM, D=64)
// ---------------------------------------------------------------------------
__global__ __launch_bounds__(256, 2) void qk_kernel(float* __restrict__ S) {
    __shared__ float Qs[16][132];
    __shared__ float Ks[16][132];
    int bh = blockIdx.z;
    int b = bh >> 4, h = bh & 15;
    const float* Qb = g_qkv + (size_t)b * SEQ * EMB + h * HDIM;
    const float* Kb = g_qkv + (size_t)NTOK * EMB + (size_t)b * SEQ * EMB + h * HDIM;
    float* Sb = S + (size_t)bh * SEQ * SEQ;
    int q0 = blockIdx.y * 128, kc0 = blockIdx.x * 128;

    int tid = threadIdx.x;
    int tx = tid & 15, ty = tid >> 4;
    int r = tid >> 2;                  // 0..63
    int dc = (tid & 3) << 2;           // 0,4,8,12

    const float* Qp = Qb + (size_t)(q0 + r) * EMB + dc;
    const float* Kp = Kb + (size_t)(kc0 + r) * EMB + dc;

    float acc[8][8];
#pragma unroll
    for (int i = 0; i < 8; i++)
#pragma unroll
        for (int j = 0; j < 8; j++) acc[i][j] = 0.0f;

    for (int d0 = 0; d0 < HDIM; d0 += 16) {
        float4 qa = *(const float4*)(Qp + d0);
        float4 qc = *(const float4*)(Qp + (size_t)64 * EMB + d0);
        float4 ka = *(const float4*)(Kp + d0);
        float4 kc4 = *(const float4*)(Kp + (size_t)64 * EMB + d0);
        __syncthreads();
        Qs[dc + 0][r] = qa.x; Qs[dc + 1][r] = qa.y; Qs[dc + 2][r] = qa.z; Qs[dc + 3][r] = qa.w;
        Qs[dc + 0][r + 64] = qc.x; Qs[dc + 1][r + 64] = qc.y; Qs[dc + 2][r + 64] = qc.z; Qs[dc + 3][r + 64] = qc.w;
        Ks[dc + 0][r] = ka.x; Ks[dc + 1][r] = ka.y; Ks[dc + 2][r] = ka.z; Ks[dc + 3][r] = ka.w;
        Ks[dc + 0][r + 64] = kc4.x; Ks[dc + 1][r + 64] = kc4.y; Ks[dc + 2][r + 64] = kc4.z; Ks[dc + 3][r + 64] = kc4.w;
        __syncthreads();
#pragma unroll
        for (int kk = 0; kk < 16; kk++) {
            float a[8], bb[8];
            *(float4*)&a[0]  = *(const float4*)&Qs[kk][ty * 8];
            *(float4*)&a[4]  = *(const float4*)&Qs[kk][ty * 8 + 4];
            *(float4*)&bb[0] = *(const float4*)&Ks[kk][tx * 8];
            *(float4*)&bb[4] = *(const float4*)&Ks[kk][tx * 8 + 4];
#pragma unroll
            for (int i = 0; i < 8; i++)
#pragma unroll
                for (int j = 0; j < 8; j++)
                    acc[i][j] = fmaf(a[i], bb[j], acc[i][j]);
        }
    }
    const float scale = 0.125f;   // 1/sqrt(64)
#pragma unroll
    for (int i = 0; i < 8; i++) {
        float* sp = Sb + (size_t)(q0 + ty * 8 + i) * SEQ + kc0 + tx * 8;
        *(float4*)sp       = make_float4(acc[i][0] * scale, acc[i][1] * scale,
                                         acc[i][2] * scale, acc[i][3] * scale);
        *(float4*)(sp + 4) = make_float4(acc[i][4] * scale, acc[i][5] * scale,
                                         acc[i][6] * scale, acc[i][7] * scale);
    }
}

// ---------------------------------------------------------------------------
// Kernel 5: in-place row softmax over rows of length SEQ (one CTA per row)
// ---------------------------------------------------------------------------
__global__ __launch_bounds__(256) void softmax_kernel(float* __restrict__ W) {
    float* p = W + (size_t)blockIdx.x * SEQ;
    int t = threadIdx.x;
    float4 a = ((float4*)p)[t];
    float4 b = ((float4*)p)[t + 256];

    float m = fmaxf(fmaxf(fmaxf(a.x, a.y), fmaxf(a.z, a.w)),
                    fmaxf(fmaxf(b.x, b.y), fmaxf(b.z, b.w)));
#pragma unroll
    for (int o = 16; o > 0; o >>= 1) m = fmaxf(m, __shfl_xor_sync(0xffffffffu, m, o));

    __shared__ float red_max[8];
    __shared__ float red_sum[8];
    if ((t & 31) == 0) red_max[t >> 5] = m;
    __syncthreads();
    if (t < 32) {
        float v = (t < 8) ? red_max[t] : -3.402823466e38f;
#pragma unroll
        for (int o = 4; o > 0; o >>= 1) v = fmaxf(v, __shfl_xor_sync(0xffffffffu, v, o));
        if (t == 0) red_max[0] = v;
    }
    __syncthreads();
    m = red_max[0];

    a.x = __expf(a.x - m); a.y = __expf(a.y - m); a.z = __expf(a.z - m); a.w = __expf(a.w - m);
    b.x = __expf(b.x - m); b.y = __expf(b.y - m); b.z = __expf(b.z - m); b.w = __expf(b.w - m);
    float s = a.x + a.y + a.z + a.w + b.x + b.y + b.z + b.w;
#pragma unroll
    for (int o = 16; o > 0; o >>= 1) s += __shfl_xor_sync(0xffffffffu, s, o);
    if ((t & 31) == 0) red_sum[t >> 5] = s;
    __syncthreads();
    if (t < 32) {
        float v = (t < 8) ? red_sum[t] : 0.0f;
#pragma unroll
        for (int o = 4; o > 0; o >>= 1) v += __shfl_xor_sync(0xffffffffu, v, o);
        if (t == 0) red_sum[0] = v;
    }
    __syncthreads();
    float inv = 1.0f / red_sum[0];

    a.x *= inv; a.y *= inv; a.z *= inv; a.w *= inv;
    b.x *= inv; b.y *= inv; b.z *= inv; b.w *= inv;
    ((float4*)p)[t] = a;
    ((float4*)p)[t + 256] = b;
}

// ---------------------------------------------------------------------------
// Kernel 6: O[bh, q, d] = sum_k P[bh,q,k] * V[bh,k,d]   (NN GEMM, N=64)
// Output written into attn_output layout [B, L, H*HDIM].
// ---------------------------------------------------------------------------
__global__ __launch_bounds__(256, 2) void pv_kernel(const float* __restrict__ P,
                                                    float* __restrict__ O) {
    __shared__ float Ps[16][132];
    __shared__ float Vs[16][64];
    int bh = blockIdx.y;
    int b = bh >> 4, h = bh & 15;
    const float* Pb = P + (size_t)bh * SEQ * SEQ;
    const float* Vb = g_qkv + (size_t)2 * NTOK * EMB + (size_t)b * SEQ * EMB + h * HDIM;
    float* Ob = O + (size_t)b * SEQ * EMB + h * HDIM;
    int q0 = blockIdx.x * 128;

    int tid = threadIdx.x;
    int tx = tid & 15, ty = tid >> 4;
    int pr = tid >> 2;                 // 0..63
    int pkc = (tid & 3) << 2;
    int vk = tid >> 4;                 // 0..15
    int vc = (tid & 15) << 2;          // 0..60

    const float* Pp = Pb + (size_t)(q0 + pr) * SEQ + pkc;
    const float* Vp0 = Vb + (size_t)vk * EMB + vc;

    float acc[8][4];
#pragma unroll
    for (int i = 0; i < 8; i++)
#pragma unroll
        for (int j = 0; j < 4; j++) acc[i][j] = 0.0f;

    for (int k0 = 0; k0 < SEQ; k0 += 16) {
        float4 p0 = *(const float4*)(Pp + k0);
        float4 p1 = *(const float4*)(Pp + (size_t)64 * SEQ + k0);
        float4 v0 = *(const float4*)(Vp0 + (size_t)k0 * EMB);
        __syncthreads();
        Ps[pkc + 0][pr] = p0.x; Ps[pkc + 1][pr] = p0.y;
        Ps[pkc + 2][pr] = p0.z; Ps[pkc + 3][pr] = p0.w;
        Ps[pkc + 0][pr + 64] = p1.x; Ps[pkc + 1][pr + 64] = p1.y;
        Ps[pkc + 2][pr + 64] = p1.z; Ps[pkc + 3][pr + 64] = p1.w;
        *(float4*)&Vs[vk][vc] = v0;
        __syncthreads();
#pragma unroll
        for (int kk = 0; kk < 16; kk++) {
            float a[8], bb[4];
            *(float4*)&a[0] = *(const float4*)&Ps[kk][ty * 8];
            *(float4*)&a[4] = *(const float4*)&Ps[kk][ty * 8 + 4];
            *(float4*)&bb[0] = *(const float4*)&Vs[kk][tx * 4];
#pragma unroll
            for (int i = 0; i < 8; i++)
#pragma unroll
                for (int j = 0; j < 4; j++)
                    acc[i][j] = fmaf(a[i], bb[j], acc[i][j]);
        }
    }
#pragma unroll
    for (int i = 0; i < 8; i++) {
        float* op = Ob + (size_t)(q0 + ty * 8 + i) * EMB + tx * 4;
        *(float4*)op = make_float4(acc[i][0], acc[i][1], acc[i][2], acc[i][3]);
    }
}

// ---------------------------------------------------------------------------
extern "C" void kernel_launch(void* const* d_in, const int* in_sizes, int n_in,
                              void* d_out, int out_size) {
    (void)in_sizes; (void)n_in; (void)out_size;
    const float* X[3] = {(const float*)d_in[0], (const float*)d_in[1], (const float*)d_in[2]};
    float* out = (float*)d_out;                          // attn_output [B, L, E]
    float* attnw = out + (size_t)NTOK * EMB;             // attn_weights [B, H, L, L]

    for (int p = 0; p < 3; p++) {
        phi_kernel<<<(NTOK * EMB) / 256, 256>>>(X[p]);
        wprep_kernel<<<(EMB * EMB) / 256, 256>>>((const float*)d_in[3 + 3 * p],
                                                 (const float*)d_in[4 + 3 * p],
                                                 (const float*)d_in[5 + 3 * p]);
        gemm_kan<<<dim3(EMB / 128, NTOK / 128), 256>>>(p);
    }
    qk_kernel<<<dim3(SEQ / 128, SEQ / 128, BATCH * HEADS), 256>>>(attnw);
    softmax_kernel<<<BATCH * HEADS * SEQ, 256>>>(attnw);
    pv_kernel<<<dim3(SEQ / 128, BATCH * HEADS), 256>>>(attnw, out);
}

// round 3
// speedup vs baseline: 1.8221x; 1.8221x over previous
#include <cuda_runtime.h>
#include <cuda_bf16.h>
#include <cstdint>
#include <cstddef>

// Problem constants
#define BATCH 2
#define SEQ   2048
#define EMB   1024
#define HEADS 16
#define HDIM  64
#define NTOK  (BATCH * SEQ)          // 4096
#define KDIM  (EMB * 8)              // 8192 expanded features
#define NB    7                      // spline bases per feature

// ---------------- scratch (static device globals; no allocation) ------------
__device__ uint4 g_phiH4[(size_t)NTOK * KDIM / 8];   // 67 MB  bf16 hi
__device__ uint4 g_phiL4[(size_t)NTOK * KDIM / 8];   // 67 MB  bf16 lo
__device__ uint4 g_WH4[(size_t)EMB * KDIM / 8];      // 16 MB  (W stored [EMB, KDIM])
__device__ uint4 g_WL4[(size_t)EMB * KDIM / 8];      // 16 MB
__device__ float g_qkv[(size_t)3 * NTOK * EMB];      // 50 MB (Q,K,V projected, fp32)

// =====================  PTX helpers (compute_103-safe: no tcgen05/TMA) ======
__device__ __forceinline__ uint32_t smem_to_u32(const void* p) {
    uint32_t a;
    asm("{ .reg .u64 t; cvta.to.shared.u64 t, %1; cvt.u32.u64 %0, t; }" : "=r"(a) : "l"(p));
    return a;
}
__device__ __forceinline__ void cp_async16(uint32_t dst, const void* src) {
    asm volatile("cp.async.cg.shared.global [%0], [%1], 16;" :: "r"(dst), "l"(src));
}
#define CP_COMMIT() asm volatile("cp.async.commit_group;" ::: "memory")
#define CP_WAIT2()  asm volatile("cp.async.wait_group 2;" ::: "memory")

__device__ __forceinline__ void ldmatrix_x4(uint32_t& r0, uint32_t& r1,
                                            uint32_t& r2, uint32_t& r3, uint32_t addr) {
    asm volatile("ldmatrix.sync.aligned.m8n8.x4.shared.b16 {%0,%1,%2,%3}, [%4];"
                 : "=r"(r0), "=r"(r1), "=r"(r2), "=r"(r3) : "r"(addr));
}
// D (fp32) += A(bf16, row) @ B(bf16, col) ; m16n8k16
__device__ __forceinline__ void mma_16816(float* d, const uint32_t* a, const uint32_t* b) {
    asm volatile(
        "mma.sync.aligned.m16n8k16.row.col.f32.bf16.bf16.f32 "
        "{%0,%1,%2,%3}, {%4,%5,%6,%7}, {%8,%9}, {%0,%1,%2,%3};"
        : "+f"(d[0]), "+f"(d[1]), "+f"(d[2]), "+f"(d[3])
        : "r"(a[0]), "r"(a[1]), "r"(a[2]), "r"(a[3]), "r"(b[0]), "r"(b[1]));
}

// ---------------------------------------------------------------------------
// Kernel 1: expand X[NTOK, EMB] -> phi rows of 8 features (x, B0..B6),
// split into bf16 hi/lo pair arrays laid out [NTOK, KDIM].
// ---------------------------------------------------------------------------
__global__ __launch_bounds__(256) void phi_split_kernel(const float* __restrict__ X) {
    int idx = blockIdx.x * blockDim.x + threadIdx.x;   // over NTOK*EMB
    if (idx >= NTOK * EMB) return;
    float x = X[idx];

    float b[10];
#pragma unroll
    for (int t = 0; t < 10; t++) {
        float gt = -2.5f + 0.5f * (float)t;
        b[t] = (x >= gt && x < gt + 0.5f) ? 1.0f : 0.0f;
    }
#pragma unroll
    for (int p = 1; p <= 3; p++) {
#pragma unroll
        for (int t = 0; t < 10; t++) {
            if (t + p < 10) {
                float gt   = -2.5f + 0.5f * (float)t;
                float gtp  = gt + 0.5f * (float)p;
                float gtp1 = gtp + 0.5f;
                float gt1  = gt + 0.5f;
                float left  = (x - gt)   / (gtp - gt);
                float right = (gtp1 - x) / (gtp1 - gt1);
                b[t] = left * b[t] + right * b[t + 1];
            }
        }
    }
    float v[8] = {x, b[0], b[1], b[2], b[3], b[4], b[5], b[6]};
    __nv_bfloat16 hi[8], lo[8];
#pragma unroll
    for (int j = 0; j < 8; j++) {
        hi[j] = __float2bfloat16(v[j]);
        lo[j] = __float2bfloat16(v[j] - __bfloat162float(hi[j]));
    }
    g_phiH4[idx] = *(uint4*)hi;
    g_phiL4[idx] = *(uint4*)lo;
}

// ---------------------------------------------------------------------------
// Kernel 2: combined weight W[EMB(out m), KDIM] row-major (K contiguous):
//   W[m, i*8+0] = base[m, i];  W[m, i*8+1+j] = spline[m, i, j] * scaler[m, i]
// ---------------------------------------------------------------------------
__global__ __launch_bounds__(256) void wprep_split_kernel(const float* __restrict__ base,
                                                          const float* __restrict__ spline,
                                                          const float* __restrict__ scaler) {
    int idx = blockIdx.x * blockDim.x + threadIdx.x;   // over EMB*EMB, i fast
    if (idx >= EMB * EMB) return;
    int i = idx & (EMB - 1);
    int m = idx >> 10;
    size_t mi = (size_t)m * EMB + i;
    float v[8];
    v[0] = base[mi];
    float sc = scaler[mi];
    const float* sp = spline + mi * NB;
#pragma unroll
    for (int j = 0; j < NB; j++) v[1 + j] = sp[j] * sc;

    __nv_bfloat16 hi[8], lo[8];
#pragma unroll
    for (int j = 0; j < 8; j++) {
        hi[j] = __float2bfloat16(v[j]);
        lo[j] = __float2bfloat16(v[j] - __bfloat162float(hi[j]));
    }
    size_t o = (size_t)m * (KDIM / 8) + i;
    g_WH4[o] = *(uint4*)hi;
    g_WL4[o] = *(uint4*)lo;
}

// ---------------------------------------------------------------------------
// Kernel 3: mma.sync GEMM  C[NTOK, EMB] = phi @ W^T, 3-term bf16 split.
// CTA tile 128(M) x 256(N) x 32(K), 8 warps (2x4), warp tile 64x64.
// 3-stage cp.async pipeline. Smem rows padded to 40 halves (80B) ->
// ldmatrix row addresses cover all 32 banks (stride 20 banks), conflict-free.
// ---------------------------------------------------------------------------
#define BM 128
#define BN 256
#define BK 32
#define NCH (KDIM / BK)                 // 256
#define ROWB 80                          // padded row bytes (40 halves)
#define A_TILE (BM * ROWB)               // 10240
#define B_TILE (BN * ROWB)               // 20480
#define STAGE (2 * A_TILE + 2 * B_TILE)  // 61440: Ah | Al | Bh | Bl
#define OFF_AH 0
#define OFF_AL A_TILE
#define OFF_BH (2 * A_TILE)
#define OFF_BL (2 * A_TILE + B_TILE)
#define GEMM_SMEM (3 * STAGE)            // 184320

__device__ __forceinline__ void load_stage(uint32_t sbase, int k0,
                                           const __nv_bfloat16* pAh, const __nv_bfloat16* pAl,
                                           const __nv_bfloat16* pBh, const __nv_bfloat16* pBl) {
    int t = threadIdx.x;
#pragma unroll
    for (int j = 0; j < 12; j++) {
        int q = j * 256 + t;             // 0..3071
        const __nv_bfloat16* src;
        uint32_t dst;
        if (j < 2) {            // Ah : q in [0,512)
            int lq = q;
            int r = lq >> 2, c = lq & 3;
            src = pAh + (size_t)r * KDIM + k0 + c * 8;
            dst = sbase + OFF_AH + r * ROWB + c * 16;
        } else if (j < 4) {     // Al : q in [512,1024)
            int lq = q - 512;
            int r = lq >> 2, c = lq & 3;
            src = pAl + (size_t)r * KDIM + k0 + c * 8;
            dst = sbase + OFF_AL + r * ROWB + c * 16;
        } else if (j < 8) {     // Bh : q in [1024,2048)
            int lq = q - 1024;
            int r = lq >> 2, c = lq & 3;
            src = pBh + (size_t)r * KDIM + k0 + c * 8;
            dst = sbase + OFF_BH + r * ROWB + c * 16;
        } else {                // Bl : q in [2048,3072)
            int lq = q - 2048;
            int r = lq >> 2, c = lq & 3;
            src = pBl + (size_t)r * KDIM + k0 + c * 8;
            dst = sbase + OFF_BL + r * ROWB + c * 16;
        }
        cp_async16(dst, src);
    }
}

__global__ __launch_bounds__(256, 1) void gemm_kan_mma(int which) {
    extern __shared__ char smem[];
    uint32_t sb = smem_to_u32(smem);
    int t = threadIdx.x;
    int lane = t & 31;
    int w = t >> 5;
    int wm = w >> 2;          // 0..1
    int wn = w & 3;           // 0..3

    int row0 = blockIdx.y * BM;
    int col0 = blockIdx.x * BN;
    const __nv_bfloat16* pAh = (const __nv_bfloat16*)g_phiH4 + (size_t)row0 * KDIM;
    const __nv_bfloat16* pAl = (const __nv_bfloat16*)g_phiL4 + (size_t)row0 * KDIM;
    const __nv_bfloat16* pBh = (const __nv_bfloat16*)g_WH4 + (size_t)col0 * KDIM;
    const __nv_bfloat16* pBl = (const __nv_bfloat16*)g_WL4 + (size_t)col0 * KDIM;

    // prologue
    load_stage(sb + 0 * STAGE, 0 * BK, pAh, pAl, pBh, pBl); CP_COMMIT();
    load_stage(sb + 1 * STAGE, 1 * BK, pAh, pAl, pBh, pBl); CP_COMMIT();
    load_stage(sb + 2 * STAGE, 2 * BK, pAh, pAl, pBh, pBl); CP_COMMIT();

    float acc[4][8][4];
#pragma unroll
    for (int i = 0; i < 4; i++)
#pragma unroll
        for (int j = 0; j < 8; j++)
#pragma unroll
            for (int q = 0; q < 4; q++) acc[i][j][q] = 0.0f;

    // ldmatrix per-lane base offsets
    int lr = lane & 15;           // row within 16
    int lh = lane >> 4;           // 16B half select
    uint32_t a_off = (uint32_t)((wm * 64 + lr) * ROWB + lh * 16);
    uint32_t b_off = (uint32_t)((wn * 64 + lr) * ROWB + lh * 16);

    for (int c = 0; c < NCH; c++) {
        int buf = c - (c / 3) * 3;
        uint32_t st = sb + buf * STAGE;
        CP_WAIT2();
        __syncthreads();

#pragma unroll
        for (int ks = 0; ks < 2; ks++) {
            uint32_t koff = ks * 32;
            uint32_t ah[4][4], al[4][4];
#pragma unroll
            for (int i = 0; i < 4; i++) {
                ldmatrix_x4(ah[i][0], ah[i][1], ah[i][2], ah[i][3],
                            st + OFF_AH + a_off + i * 16 * ROWB + koff);
                ldmatrix_x4(al[i][0], al[i][1], al[i][2], al[i][3],
                            st + OFF_AL + a_off + i * 16 * ROWB + koff);
            }
            uint32_t bh[4][4], bl[4][4];
#pragma unroll
            for (int p = 0; p < 4; p++) {       // 4 n16 groups
                ldmatrix_x4(bh[p][0], bh[p][1], bh[p][2], bh[p][3],
                            st + OFF_BH + b_off + p * 16 * ROWB + koff);
                ldmatrix_x4(bl[p][0], bl[p][1], bl[p][2], bl[p][3],
                            st + OFF_BL + b_off + p * 16 * ROWB + koff);
            }
#pragma unroll
            for (int i = 0; i < 4; i++) {
#pragma unroll
                for (int p = 0; p < 4; p++) {
                    uint32_t b0h[2] = {bh[p][0], bh[p][2]};   // n-tile p*2
                    uint32_t b1h[2] = {bh[p][1], bh[p][3]};   // n-tile p*2+1
                    uint32_t b0l[2] = {bl[p][0], bl[p][2]};
                    uint32_t b1l[2] = {bl[p][1], bl[p][3]};
                    mma_16816(acc[i][p * 2 + 0], ah[i], b0h);
                    mma_16816(acc[i][p * 2 + 1], ah[i], b1h);
                    mma_16816(acc[i][p * 2 + 0], ah[i], b0l);
                    mma_16816(acc[i][p * 2 + 1], ah[i], b1l);
                    mma_16816(acc[i][p * 2 + 0], al[i], b0h);
                    mma_16816(acc[i][p * 2 + 1], al[i], b1h);
                }
            }
        }
        __syncthreads();
        if (c + 3 < NCH) load_stage(st, (c + 3) * BK, pAh, pAl, pBh, pBl);
        CP_COMMIT();   // empty group when no loads -> wait_group stays exact
    }

    // epilogue: fp32 accumulators -> g_qkv
    float* C = g_qkv + (size_t)which * NTOK * EMB;
    int mbase = row0 + wm * 64 + (lane >> 2);
    int nbase = col0 + wn * 64 + (lane & 3) * 2;
#pragma unroll
    for (int i = 0; i < 4; i++) {
#pragma unroll
        for (int j = 0; j < 8; j++) {
            float* p0 = C + (size_t)(mbase + i * 16) * EMB + nbase + j * 8;
            float* p1 = p0 + 8 * EMB;
            *(float2*)p0 = make_float2(acc[i][j][0], acc[i][j][1]);
            *(float2*)p1 = make_float2(acc[i][j][2], acc[i][j][3]);
        }
    }
}

// ---------------------------------------------------------------------------
// Kernel 4: scores S[bh, q, k] = (Q . K) / 8   (fp32 SIMT)
// ---------------------------------------------------------------------------
__global__ __launch_bounds__(256, 2) void qk_kernel(float* __restrict__ S) {
    __shared__ float Qs[16][132];
    __shared__ float Ks[16][132];
    int bh = blockIdx.z;
    int b = bh >> 4, h = bh & 15;
    const float* Qb = g_qkv + (size_t)b * SEQ * EMB + h * HDIM;
    const float* Kb = g_qkv + (size_t)NTOK * EMB + (size_t)b * SEQ * EMB + h * HDIM;
    float* Sb = S + (size_t)bh * SEQ * SEQ;
    int q0 = blockIdx.y * 128, kc0 = blockIdx.x * 128;

    int tid = threadIdx.x;
    int tx = tid & 15, ty = tid >> 4;
    int r = tid >> 2;
    int dc = (tid & 3) << 2;

    const float* Qp = Qb + (size_t)(q0 + r) * EMB + dc;
    const float* Kp = Kb + (size_t)(kc0 + r) * EMB + dc;

    float acc[8][8];
#pragma unroll
    for (int i = 0; i < 8; i++)
#pragma unroll
        for (int j = 0; j < 8; j++) acc[i][j] = 0.0f;

    for (int d0 = 0; d0 < HDIM; d0 += 16) {
        float4 qa = *(const float4*)(Qp + d0);
        float4 qc = *(const float4*)(Qp + (size_t)64 * EMB + d0);
        float4 ka = *(const float4*)(Kp + d0);
        float4 kc4 = *(const float4*)(Kp + (size_t)64 * EMB + d0);
        __syncthreads();
        Qs[dc + 0][r] = qa.x; Qs[dc + 1][r] = qa.y; Qs[dc + 2][r] = qa.z; Qs[dc + 3][r] = qa.w;
        Qs[dc + 0][r + 64] = qc.x; Qs[dc + 1][r + 64] = qc.y; Qs[dc + 2][r + 64] = qc.z; Qs[dc + 3][r + 64] = qc.w;
        Ks[dc + 0][r] = ka.x; Ks[dc + 1][r] = ka.y; Ks[dc + 2][r] = ka.z; Ks[dc + 3][r] = ka.w;
        Ks[dc + 0][r + 64] = kc4.x; Ks[dc + 1][r + 64] = kc4.y; Ks[dc + 2][r + 64] = kc4.z; Ks[dc + 3][r + 64] = kc4.w;
        __syncthreads();
#pragma unroll
        for (int kk = 0; kk < 16; kk++) {
            float a[8], bb[8];
            *(float4*)&a[0]  = *(const float4*)&Qs[kk][ty * 8];
            *(float4*)&a[4]  = *(const float4*)&Qs[kk][ty * 8 + 4];
            *(float4*)&bb[0] = *(const float4*)&Ks[kk][tx * 8];
            *(float4*)&bb[4] = *(const float4*)&Ks[kk][tx * 8 + 4];
#pragma unroll
            for (int i = 0; i < 8; i++)
#pragma unroll
                for (int j = 0; j < 8; j++)
                    acc[i][j] = fmaf(a[i], bb[j], acc[i][j]);
        }
    }
    const float scale = 0.125f;
#pragma unroll
    for (int i = 0; i < 8; i++) {
        float* sp = Sb + (size_t)(q0 + ty * 8 + i) * SEQ + kc0 + tx * 8;
        *(float4*)sp       = make_float4(acc[i][0] * scale, acc[i][1] * scale,
                                         acc[i][2] * scale, acc[i][3] * scale);
        *(float4*)(sp + 4) = make_float4(acc[i][4] * scale, acc[i][5] * scale,
                                         acc[i][6] * scale, acc[i][7] * scale);
    }
}

// ---------------------------------------------------------------------------
// Kernel 5: in-place row softmax (one CTA per row of length SEQ)
// ---------------------------------------------------------------------------
__global__ __launch_bounds__(256) void softmax_kernel(float* __restrict__ W) {
    float* p = W + (size_t)blockIdx.x * SEQ;
    int t = threadIdx.x;
    float4 a = ((float4*)p)[t];
    float4 b = ((float4*)p)[t + 256];

    float m = fmaxf(fmaxf(fmaxf(a.x, a.y), fmaxf(a.z, a.w)),
                    fmaxf(fmaxf(b.x, b.y), fmaxf(b.z, b.w)));
#pragma unroll
    for (int o = 16; o > 0; o >>= 1) m = fmaxf(m, __shfl_xor_sync(0xffffffffu, m, o));

    __shared__ float red_max[8];
    __shared__ float red_sum[8];
    if ((t & 31) == 0) red_max[t >> 5] = m;
    __syncthreads();
    if (t < 32) {
        float v = (t < 8) ? red_max[t] : -3.402823466e38f;
#pragma unroll
        for (int o = 4; o > 0; o >>= 1) v = fmaxf(v, __shfl_xor_sync(0xffffffffu, v, o));
        if (t == 0) red_max[0] = v;
    }
    __syncthreads();
    m = red_max[0];

    a.x = __expf(a.x - m); a.y = __expf(a.y - m); a.z = __expf(a.z - m); a.w = __expf(a.w - m);
    b.x = __expf(b.x - m); b.y = __expf(b.y - m); b.z = __expf(b.z - m); b.w = __expf(b.w - m);
    float s = a.x + a.y + a.z + a.w + b.x + b.y + b.z + b.w;
#pragma unroll
    for (int o = 16; o > 0; o >>= 1) s += __shfl_xor_sync(0xffffffffu, s, o);
    if ((t & 31) == 0) red_sum[t >> 5] = s;
    __syncthreads();
    if (t < 32) {
        float v = (t < 8) ? red_sum[t] : 0.0f;
#pragma unroll
        for (int o = 4; o > 0; o >>= 1) v += __shfl_xor_sync(0xffffffffu, v, o);
        if (t == 0) red_sum[0] = v;
    }
    __syncthreads();
    float inv = 1.0f / red_sum[0];

    a.x *= inv; a.y *= inv; a.z *= inv; a.w *= inv;
    b.x *= inv; b.y *= inv; b.z *= inv; b.w *= inv;
    ((float4*)p)[t] = a;
    ((float4*)p)[t + 256] = b;
}

// ---------------------------------------------------------------------------
// Kernel 6: O = P @ V   (fp32 SIMT, N=64 per head)
// ---------------------------------------------------------------------------
__global__ __launch_bounds__(256, 2) void pv_kernel(const float* __restrict__ P,
                                                    float* __restrict__ O) {
    __shared__ float Ps[16][132];
    __shared__ float Vs[16][64];
    int bh = blockIdx.y;
    int b = bh >> 4, h = bh & 15;
    const float* Pb = P + (size_t)bh * SEQ * SEQ;
    const float* Vb = g_qkv + (size_t)2 * NTOK * EMB + (size_t)b * SEQ * EMB + h * HDIM;
    float* Ob = O + (size_t)b * SEQ * EMB + h * HDIM;
    int q0 = blockIdx.x * 128;

    int tid = threadIdx.x;
    int tx = tid & 15, ty = tid >> 4;
    int pr = tid >> 2;
    int pkc = (tid & 3) << 2;
    int vk = tid >> 4;
    int vc = (tid & 15) << 2;

    const float* Pp = Pb + (size_t)(q0 + pr) * SEQ + pkc;
    const float* Vp0 = Vb + (size_t)vk * EMB + vc;

    float acc[8][4];
#pragma unroll
    for (int i = 0; i < 8; i++)
#pragma unroll
        for (int j = 0; j < 4; j++) acc[i][j] = 0.0f;

    for (int k0 = 0; k0 < SEQ; k0 += 16) {
        float4 p0 = *(const float4*)(Pp + k0);
        float4 p1 = *(const float4*)(Pp + (size_t)64 * SEQ + k0);
        float4 v0 = *(const float4*)(Vp0 + (size_t)k0 * EMB);
        __syncthreads();
        Ps[pkc + 0][pr] = p0.x; Ps[pkc + 1][pr] = p0.y;
        Ps[pkc + 2][pr] = p0.z; Ps[pkc + 3][pr] = p0.w;
        Ps[pkc + 0][pr + 64] = p1.x; Ps[pkc + 1][pr + 64] = p1.y;
        Ps[pkc + 2][pr + 64] = p1.z; Ps[pkc + 3][pr + 64] = p1.w;
        *(float4*)&Vs[vk][vc] = v0;
        __syncthreads();
#pragma unroll
        for (int kk = 0; kk < 16; kk++) {
            float a[8], bb[4];
            *(float4*)&a[0] = *(const float4*)&Ps[kk][ty * 8];
            *(float4*)&a[4] = *(const float4*)&Ps[kk][ty * 8 + 4];
            *(float4*)&bb[0] = *(const float4*)&Vs[kk][tx * 4];
#pragma unroll
            for (int i = 0; i < 8; i++)
#pragma unroll
                for (int j = 0; j < 4; j++)
                    acc[i][j] = fmaf(a[i], bb[j], acc[i][j]);
        }
    }
#pragma unroll
    for (int i = 0; i < 8; i++) {
        float* op = Ob + (size_t)(q0 + ty * 8 + i) * EMB + tx * 4;
        *(float4*)op = make_float4(acc[i][0], acc[i][1], acc[i][2], acc[i][3]);
    }
}

// ---------------------------------------------------------------------------
extern "C" void kernel_launch(void* const* d_in, const int* in_sizes, int n_in,
                              void* d_out, int out_size) {
    (void)in_sizes; (void)n_in; (void)out_size;
    const float* X[3] = {(const float*)d_in[0], (const float*)d_in[1], (const float*)d_in[2]};
    float* out = (float*)d_out;                          // attn_output [B, L, E]
    float* attnw = out + (size_t)NTOK * EMB;             // attn_weights [B, H, L, L]

    cudaFuncSetAttribute(gemm_kan_mma, cudaFuncAttributeMaxDynamicSharedMemorySize,
                         GEMM_SMEM);

    for (int p = 0; p < 3; p++) {
        phi_split_kernel<<<(NTOK * EMB) / 256, 256>>>(X[p]);
        wprep_split_kernel<<<(EMB * EMB) / 256, 256>>>((const float*)d_in[3 + 3 * p],
                                                       (const float*)d_in[4 + 3 * p],
                                                       (const float*)d_in[5 + 3 * p]);
        gemm_kan_mma<<<dim3(EMB / BN, NTOK / BM), 256, GEMM_SMEM>>>(p);
    }
    qk_kernel<<<dim3(SEQ / 128, SEQ / 128, BATCH * HEADS), 256>>>(attnw);
    softmax_kernel<<<BATCH * HEADS * SEQ, 256>>>(attnw);
    pv_kernel<<<dim3(SEQ / 128, BATCH * HEADS), 256>>>(attnw, out);
}

// round 6
// speedup vs baseline: 2.1319x; 1.1700x over previous
#include <cuda_runtime.h>
#include <cuda_bf16.h>
#include <cstdint>
#include <cstddef>

// Problem constants
#define BATCH 2
#define SEQ   2048
#define EMB   1024
#define HEADS 16
#define HDIM  64
#define NTOK  (BATCH * SEQ)          // 4096
#define KDIM  (EMB * 8)              // 8192 expanded features
#define NB    7                      // spline bases per feature

// ---------------- scratch (static device globals; no allocation) ------------
__device__ uint4 g_phiH4[(size_t)NTOK * KDIM / 8];   // 67 MB  bf16 hi
__device__ uint4 g_phiL4[(size_t)NTOK * KDIM / 8];   // 67 MB  bf16 lo
__device__ uint4 g_WH4[(size_t)EMB * KDIM / 8];      // 16 MB  (W stored [EMB, KDIM])
__device__ uint4 g_WL4[(size_t)EMB * KDIM / 8];      // 16 MB
// projected Q,K,V as bf16 hi/lo split, layout [3][NTOK][EMB]
__device__ __nv_bfloat16 g_qkvH[(size_t)3 * NTOK * EMB];  // 25 MB
__device__ __nv_bfloat16 g_qkvL[(size_t)3 * NTOK * EMB];  // 25 MB

// =====================  PTX helpers (compute_103-safe) ======================
__device__ __forceinline__ uint32_t smem_to_u32(const void* p) {
    uint32_t a;
    asm("{ .reg .u64 t; cvta.to.shared.u64 t, %1; cvt.u32.u64 %0, t; }" : "=r"(a) : "l"(p));
    return a;
}
__device__ __forceinline__ void cp_async16(uint32_t dst, const void* src) {
    asm volatile("cp.async.cg.shared.global [%0], [%1], 16;" :: "r"(dst), "l"(src));
}
#define CP_COMMIT() asm volatile("cp.async.commit_group;" ::: "memory")
#define CP_WAIT2()  asm volatile("cp.async.wait_group 2;" ::: "memory")
#define CP_WAIT0()  asm volatile("cp.async.wait_group 0;" ::: "memory")

__device__ __forceinline__ void ldmatrix_x4(uint32_t& r0, uint32_t& r1,
                                            uint32_t& r2, uint32_t& r3, uint32_t addr) {
    asm volatile("ldmatrix.sync.aligned.m8n8.x4.shared.b16 {%0,%1,%2,%3}, [%4];"
                 : "=r"(r0), "=r"(r1), "=r"(r2), "=r"(r3) : "r"(addr));
}
__device__ __forceinline__ void ldmatrix_x4_trans(uint32_t& r0, uint32_t& r1,
                                                  uint32_t& r2, uint32_t& r3, uint32_t addr) {
    asm volatile("ldmatrix.sync.aligned.m8n8.x4.trans.shared.b16 {%0,%1,%2,%3}, [%4];"
                 : "=r"(r0), "=r"(r1), "=r"(r2), "=r"(r3) : "r"(addr));
}
// D (fp32) += A(bf16, row) @ B(bf16, col) ; m16n8k16
__device__ __forceinline__ void mma_16816(float* d, const uint32_t* a, const uint32_t* b) {
    asm volatile(
        "mma.sync.aligned.m16n8k16.row.col.f32.bf16.bf16.f32 "
        "{%0,%1,%2,%3}, {%4,%5,%6,%7}, {%8,%9}, {%0,%1,%2,%3};"
        : "+f"(d[0]), "+f"(d[1]), "+f"(d[2]), "+f"(d[3])
        : "r"(a[0]), "r"(a[1]), "r"(a[2]), "r"(a[3]), "r"(b[0]), "r"(b[1]));
}
__device__ __forceinline__ void split_bf16(float v, __nv_bfloat16& h, __nv_bfloat16& l) {
    h = __float2bfloat16(v);
    l = __float2bfloat16(v - __bfloat162float(h));
}

// ---------------------------------------------------------------------------
// Kernel 1: expand X[NTOK, EMB] -> phi (x, B0..B6) bf16 hi/lo, [NTOK, KDIM]
// ---------------------------------------------------------------------------
__global__ __launch_bounds__(256) void phi_split_kernel(const float* __restrict__ X) {
    int idx = blockIdx.x * blockDim.x + threadIdx.x;
    if (idx >= NTOK * EMB) return;
    float x = X[idx];

    float b[10];
#pragma unroll
    for (int t = 0; t < 10; t++) {
        float gt = -2.5f + 0.5f * (float)t;
        b[t] = (x >= gt && x < gt + 0.5f) ? 1.0f : 0.0f;
    }
#pragma unroll
    for (int p = 1; p <= 3; p++) {
#pragma unroll
        for (int t = 0; t < 10; t++) {
            if (t + p < 10) {
                float gt   = -2.5f + 0.5f * (float)t;
                float gtp  = gt + 0.5f * (float)p;
                float gtp1 = gtp + 0.5f;
                float gt1  = gt + 0.5f;
                float left  = (x - gt)   / (gtp - gt);
                float right = (gtp1 - x) / (gtp1 - gt1);
                b[t] = left * b[t] + right * b[t + 1];
            }
        }
    }
    float v[8] = {x, b[0], b[1], b[2], b[3], b[4], b[5], b[6]};
    __nv_bfloat16 hi[8], lo[8];
#pragma unroll
    for (int j = 0; j < 8; j++) split_bf16(v[j], hi[j], lo[j]);
    g_phiH4[idx] = *(uint4*)hi;
    g_phiL4[idx] = *(uint4*)lo;
}

// ---------------------------------------------------------------------------
// Kernel 2: combined weight W[EMB(out m), KDIM] row-major, bf16 hi/lo
// ---------------------------------------------------------------------------
__global__ __launch_bounds__(256) void wprep_split_kernel(const float* __restrict__ base,
                                                          const float* __restrict__ spline,
                                                          const float* __restrict__ scaler) {
    int idx = blockIdx.x * blockDim.x + threadIdx.x;
    if (idx >= EMB * EMB) return;
    int i = idx & (EMB - 1);
    int m = idx >> 10;
    size_t mi = (size_t)m * EMB + i;
    float v[8];
    v[0] = base[mi];
    float sc = scaler[mi];
    const float* sp = spline + mi * NB;
#pragma unroll
    for (int j = 0; j < NB; j++) v[1 + j] = sp[j] * sc;

    __nv_bfloat16 hi[8], lo[8];
#pragma unroll
    for (int j = 0; j < 8; j++) split_bf16(v[j], hi[j], lo[j]);
    size_t o = (size_t)m * (KDIM / 8) + i;
    g_WH4[o] = *(uint4*)hi;
    g_WL4[o] = *(uint4*)lo;
}

// ---------------------------------------------------------------------------
// Kernel 3: mma.sync GEMM  C = phi @ W^T, 3-term bf16 split.
// CTA 128x256x32, 8 warps (2x4), warp tile 64x64, 3-stage cp.async.
// Epilogue writes bf16 hi/lo split directly (for attention mma kernels).
// ---------------------------------------------------------------------------
#define BM 128
#define BN 256
#define BK 32
#define NCH (KDIM / BK)                 // 256
#define ROWB 80
#define A_TILE (BM * ROWB)
#define B_TILE (BN * ROWB)
#define STAGE (2 * A_TILE + 2 * B_TILE)
#define OFF_AH 0
#define OFF_AL A_TILE
#define OFF_BH (2 * A_TILE)
#define OFF_BL (2 * A_TILE + B_TILE)
#define GEMM_SMEM (3 * STAGE)

__device__ __forceinline__ void load_stage(uint32_t sbase, int k0,
                                           const __nv_bfloat16* pAh, const __nv_bfloat16* pAl,
                                           const __nv_bfloat16* pBh, const __nv_bfloat16* pBl) {
    int t = threadIdx.x;
#pragma unroll
    for (int j = 0; j < 12; j++) {
        int q = j * 256 + t;
        const __nv_bfloat16* src;
        uint32_t dst;
        if (j < 2) {
            int lq = q;
            int r = lq >> 2, c = lq & 3;
            src = pAh + (size_t)r * KDIM + k0 + c * 8;
            dst = sbase + OFF_AH + r * ROWB + c * 16;
        } else if (j < 4) {
            int lq = q - 512;
            int r = lq >> 2, c = lq & 3;
            src = pAl + (size_t)r * KDIM + k0 + c * 8;
            dst = sbase + OFF_AL + r * ROWB + c * 16;
        } else if (j < 8) {
            int lq = q - 1024;
            int r = lq >> 2, c = lq & 3;
            src = pBh + (size_t)r * KDIM + k0 + c * 8;
            dst = sbase + OFF_BH + r * ROWB + c * 16;
        } else {
            int lq = q - 2048;
            int r = lq >> 2, c = lq & 3;
            src = pBl + (size_t)r * KDIM + k0 + c * 8;
            dst = sbase + OFF_BL + r * ROWB + c * 16;
        }
        cp_async16(dst, src);
    }
}

__global__ __launch_bounds__(256, 1) void gemm_kan_mma(int which) {
    extern __shared__ char smem[];
    uint32_t sb = smem_to_u32(smem);
    int t = threadIdx.x;
    int lane = t & 31;
    int w = t >> 5;
    int wm = w >> 2;
    int wn = w & 3;

    int row0 = blockIdx.y * BM;
    int col0 = blockIdx.x * BN;
    const __nv_bfloat16* pAh = (const __nv_bfloat16*)g_phiH4 + (size_t)row0 * KDIM;
    const __nv_bfloat16* pAl = (const __nv_bfloat16*)g_phiL4 + (size_t)row0 * KDIM;
    const __nv_bfloat16* pBh = (const __nv_bfloat16*)g_WH4 + (size_t)col0 * KDIM;
    const __nv_bfloat16* pBl = (const __nv_bfloat16*)g_WL4 + (size_t)col0 * KDIM;

    load_stage(sb + 0 * STAGE, 0 * BK, pAh, pAl, pBh, pBl); CP_COMMIT();
    load_stage(sb + 1 * STAGE, 1 * BK, pAh, pAl, pBh, pBl); CP_COMMIT();
    load_stage(sb + 2 * STAGE, 2 * BK, pAh, pAl, pBh, pBl); CP_COMMIT();

    float acc[4][8][4];
#pragma unroll
    for (int i = 0; i < 4; i++)
#pragma unroll
        for (int j = 0; j < 8; j++)
#pragma unroll
            for (int q = 0; q < 4; q++) acc[i][j][q] = 0.0f;

    int lr = lane & 15;
    int lh = lane >> 4;
    uint32_t a_off = (uint32_t)((wm * 64 + lr) * ROWB + lh * 16);
    uint32_t b_off = (uint32_t)((wn * 64 + lr) * ROWB + lh * 16);

    for (int c = 0; c < NCH; c++) {
        int buf = c - (c / 3) * 3;
        uint32_t st = sb + buf * STAGE;
        CP_WAIT2();
        __syncthreads();

#pragma unroll
        for (int ks = 0; ks < 2; ks++) {
            uint32_t koff = ks * 32;
            uint32_t ah[4][4], al[4][4];
#pragma unroll
            for (int i = 0; i < 4; i++) {
                ldmatrix_x4(ah[i][0], ah[i][1], ah[i][2], ah[i][3],
                            st + OFF_AH + a_off + i * 16 * ROWB + koff);
                ldmatrix_x4(al[i][0], al[i][1], al[i][2], al[i][3],
                            st + OFF_AL + a_off + i * 16 * ROWB + koff);
            }
            uint32_t bh[4][4], bl[4][4];
#pragma unroll
            for (int p = 0; p < 4; p++) {
                ldmatrix_x4(bh[p][0], bh[p][1], bh[p][2], bh[p][3],
                            st + OFF_BH + b_off + p * 16 * ROWB + koff);
                ldmatrix_x4(bl[p][0], bl[p][1], bl[p][2], bl[p][3],
                            st + OFF_BL + b_off + p * 16 * ROWB + koff);
            }
#pragma unroll
            for (int i = 0; i < 4; i++) {
#pragma unroll
                for (int p = 0; p < 4; p++) {
                    uint32_t b0h[2] = {bh[p][0], bh[p][2]};
                    uint32_t b1h[2] = {bh[p][1], bh[p][3]};
                    uint32_t b0l[2] = {bl[p][0], bl[p][2]};
                    uint32_t b1l[2] = {bl[p][1], bl[p][3]};
                    mma_16816(acc[i][p * 2 + 0], ah[i], b0h);
                    mma_16816(acc[i][p * 2 + 1], ah[i], b1h);
                    mma_16816(acc[i][p * 2 + 0], ah[i], b0l);
                    mma_16816(acc[i][p * 2 + 1], ah[i], b1l);
                    mma_16816(acc[i][p * 2 + 0], al[i], b0h);
                    mma_16816(acc[i][p * 2 + 1], al[i], b1h);
                }
            }
        }
        __syncthreads();
        if (c + 3 < NCH) load_stage(st, (c + 3) * BK, pAh, pAl, pBh, pBl);
        CP_COMMIT();
    }

    // epilogue: split fp32 accumulators to bf16 hi/lo and store
    __nv_bfloat16* CH = g_qkvH + (size_t)which * NTOK * EMB;
    __nv_bfloat16* CL = g_qkvL + (size_t)which * NTOK * EMB;
    int mbase = row0 + wm * 64 + (lane >> 2);
    int nbase = col0 + wn * 64 + (lane & 3) * 2;
#pragma unroll
    for (int i = 0; i < 4; i++) {
#pragma unroll
        for (int j = 0; j < 8; j++) {
            size_t o0 = (size_t)(mbase + i * 16) * EMB + nbase + j * 8;
            size_t o1 = o0 + (size_t)8 * EMB;
            __nv_bfloat162 h2, l2;
            split_bf16(acc[i][j][0], h2.x, l2.x);
            split_bf16(acc[i][j][1], h2.y, l2.y);
            *(uint32_t*)(CH + o0) = *(uint32_t*)&h2;
            *(uint32_t*)(CL + o0) = *(uint32_t*)&l2;
            split_bf16(acc[i][j][2], h2.x, l2.x);
            split_bf16(acc[i][j][3], h2.y, l2.y);
            *(uint32_t*)(CH + o1) = *(uint32_t*)&h2;
            *(uint32_t*)(CL + o1) = *(uint32_t*)&l2;
        }
    }
}

// ---------------------------------------------------------------------------
// Kernel 4: scores via mma, 3-term split. CTA = (bh, 128q, 128k), one-shot.
// Smem rows padded to 144B -> conflict-free ldmatrix.
// ---------------------------------------------------------------------------
#define QK_ROWB 144
#define QK_TILE (128 * QK_ROWB)          // 18432
#define QK_QH 0
#define QK_QL QK_TILE
#define QK_KH (2 * QK_TILE)
#define QK_KL (3 * QK_TILE)
#define QK_SMEM (4 * QK_TILE)            // 73728

__global__ __launch_bounds__(256, 2) void qk_mma(float* __restrict__ S) {
    extern __shared__ char smem[];
    uint32_t sb = smem_to_u32(smem);
    int t = threadIdx.x;
    int lane = t & 31;
    int w = t >> 5;
    int wm = w >> 1;          // 0..3: 32 q-rows each
    int wn = w & 1;           // 0..1: 64 k-cols each

    int bh = blockIdx.z;
    int b = bh >> 4, h = bh & 15;
    int q0 = blockIdx.y * 128;
    int k0 = blockIdx.x * 128;

    const __nv_bfloat16* QH = g_qkvH + ((size_t)(b * SEQ + q0)) * EMB + h * HDIM;
    const __nv_bfloat16* QL = g_qkvL + ((size_t)(b * SEQ + q0)) * EMB + h * HDIM;
    const __nv_bfloat16* KH = g_qkvH + (size_t)NTOK * EMB + ((size_t)(b * SEQ + k0)) * EMB + h * HDIM;
    const __nv_bfloat16* KL = g_qkvL + (size_t)NTOK * EMB + ((size_t)(b * SEQ + k0)) * EMB + h * HDIM;

    // load 4 tiles of 128 rows x 64 bf16 (8 x 16B per row)
    {
        const __nv_bfloat16* srcs[4] = {QH, QL, KH, KL};
        uint32_t dsts[4] = {sb + QK_QH, sb + QK_QL, sb + QK_KH, sb + QK_KL};
#pragma unroll
        for (int j = 0; j < 16; j++) {
            int q = j * 256 + t;          // 0..4095
            int op = q >> 10;
            int r = (q >> 3) & 127;
            int c = q & 7;
            cp_async16(dsts[op] + r * QK_ROWB + c * 16,
                       srcs[op] + (size_t)r * EMB + c * 8);
        }
    }
    CP_COMMIT();
    CP_WAIT0();
    __syncthreads();

    float acc[2][8][4];
#pragma unroll
    for (int i = 0; i < 2; i++)
#pragma unroll
        for (int j = 0; j < 8; j++)
#pragma unroll
            for (int q = 0; q < 4; q++) acc[i][j][q] = 0.0f;

    int lr = lane & 15;
    int lh = lane >> 4;
    uint32_t a_off = (uint32_t)((wm * 32 + lr) * QK_ROWB + lh * 16);
    uint32_t b_off = (uint32_t)((wn * 64 + lr) * QK_ROWB + lh * 16);

#pragma unroll
    for (int ks = 0; ks < 4; ks++) {
        uint32_t koff = ks * 32;
        uint32_t ah[2][4], al[2][4];
#pragma unroll
        for (int mi = 0; mi < 2; mi++) {
            ldmatrix_x4(ah[mi][0], ah[mi][1], ah[mi][2], ah[mi][3],
                        sb + QK_QH + a_off + mi * 16 * QK_ROWB + koff);
            ldmatrix_x4(al[mi][0], al[mi][1], al[mi][2], al[mi][3],
                        sb + QK_QL + a_off + mi * 16 * QK_ROWB + koff);
        }
#pragma unroll
        for (int p = 0; p < 4; p++) {
            uint32_t kh[4], kl[4];
            ldmatrix_x4(kh[0], kh[1], kh[2], kh[3],
                        sb + QK_KH + b_off + p * 16 * QK_ROWB + koff);
            ldmatrix_x4(kl[0], kl[1], kl[2], kl[3],
                        sb + QK_KL + b_off + p * 16 * QK_ROWB + koff);
            uint32_t b0h[2] = {kh[0], kh[2]};
            uint32_t b1h[2] = {kh[1], kh[3]};
            uint32_t b0l[2] = {kl[0], kl[2]};
            uint32_t b1l[2] = {kl[1], kl[3]};
#pragma unroll
            for (int mi = 0; mi < 2; mi++) {
                mma_16816(acc[mi][p * 2 + 0], ah[mi], b0h);
                mma_16816(acc[mi][p * 2 + 1], ah[mi], b1h);
                mma_16816(acc[mi][p * 2 + 0], ah[mi], b0l);
                mma_16816(acc[mi][p * 2 + 1], ah[mi], b1l);
                mma_16816(acc[mi][p * 2 + 0], al[mi], b0h);
                mma_16816(acc[mi][p * 2 + 1], al[mi], b1h);
            }
        }
    }

    float* Sb = S + (size_t)bh * SEQ * SEQ;
    const float scale = 0.125f;
#pragma unroll
    for (int mi = 0; mi < 2; mi++) {
        int r0 = q0 + wm * 32 + mi * 16 + (lane >> 2);
#pragma unroll
        for (int n = 0; n < 8; n++) {
            int col = k0 + wn * 64 + n * 8 + (lane & 3) * 2;
            *(float2*)(Sb + (size_t)r0 * SEQ + col) =
                make_float2(acc[mi][n][0] * scale, acc[mi][n][1] * scale);
            *(float2*)(Sb + (size_t)(r0 + 8) * SEQ + col) =
                make_float2(acc[mi][n][2] * scale, acc[mi][n][3] * scale);
        }
    }
}

// ---------------------------------------------------------------------------
// Kernel 5: in-place row softmax (one CTA per row of length SEQ)
// ---------------------------------------------------------------------------
__global__ __launch_bounds__(256) void softmax_kernel(float* __restrict__ W) {
    float* p = W + (size_t)blockIdx.x * SEQ;
    int t = threadIdx.x;
    float4 a = ((float4*)p)[t];
    float4 b = ((float4*)p)[t + 256];

    float m = fmaxf(fmaxf(fmaxf(a.x, a.y), fmaxf(a.z, a.w)),
                    fmaxf(fmaxf(b.x, b.y), fmaxf(b.z, b.w)));
#pragma unroll
    for (int o = 16; o > 0; o >>= 1) m = fmaxf(m, __shfl_xor_sync(0xffffffffu, m, o));

    __shared__ float red_max[8];
    __shared__ float red_sum[8];
    if ((t & 31) == 0) red_max[t >> 5] = m;
    __syncthreads();
    if (t < 32) {
        float v = (t < 8) ? red_max[t] : -3.402823466e38f;
#pragma unroll
        for (int o = 4; o > 0; o >>= 1) v = fmaxf(v, __shfl_xor_sync(0xffffffffu, v, o));
        if (t == 0) red_max[0] = v;
    }
    __syncthreads();
    m = red_max[0];

    a.x = __expf(a.x - m); a.y = __expf(a.y - m); a.z = __expf(a.z - m); a.w = __expf(a.w - m);
    b.x = __expf(b.x - m); b.y = __expf(b.y - m); b.z = __expf(b.z - m); b.w = __expf(b.w - m);
    float s = a.x + a.y + a.z + a.w + b.x + b.y + b.z + b.w;
#pragma unroll
    for (int o = 16; o > 0; o >>= 1) s += __shfl_xor_sync(0xffffffffu, s, o);
    if ((t & 31) == 0) red_sum[t >> 5] = s;
    __syncthreads();
    if (t < 32) {
        float v = (t < 8) ? red_sum[t] : 0.0f;
#pragma unroll
        for (int o = 4; o > 0; o >>= 1) v += __shfl_xor_sync(0xffffffffu, v, o);
        if (t == 0) red_sum[0] = v;
    }
    __syncthreads();
    float inv = 1.0f / red_sum[0];

    a.x *= inv; a.y *= inv; a.z *= inv; a.w *= inv;
    b.x *= inv; b.y *= inv; b.z *= inv; b.w *= inv;
    ((float4*)p)[t] = a;
    ((float4*)p)[t + 256] = b;
}

// ---------------------------------------------------------------------------
// Kernel 6: O = P @ V via mma, 3-term split (PhVh + PhVl + PlVh).
// CTA = (bh, 128q); loops 16 chunks of 128 k. P converted fp32->hi/lo on fly.
// V kept k-major in smem [128 seq][64 d]; consumed with ldmatrix.x4.trans
// (trans fragment pairing: {v0,v1} = n-subtile 0, {v2,v3} = n-subtile 1).
// ---------------------------------------------------------------------------
#define PV_PROWB 272                     // 128 bf16 + 16B pad
#define PV_VROWB 144
#define PV_PH 0
#define PV_PL (128 * PV_PROWB)                       // 34816
#define PV_VH (2 * 128 * PV_PROWB)                   // 69632
#define PV_VL (2 * 128 * PV_PROWB + 128 * PV_VROWB)  // 88064
#define PV_SMEM (2 * 128 * PV_PROWB + 2 * 128 * PV_VROWB)  // 106496

__global__ __launch_bounds__(256, 2) void pv_mma(const float* __restrict__ P,
                                                 float* __restrict__ O) {
    extern __shared__ char smem[];
    uint32_t sb = smem_to_u32(smem);
    int t = threadIdx.x;
    int lane = t & 31;
    int w = t >> 5;
    int wm = w >> 1;          // 0..3: 32 q-rows
    int wn = w & 1;           // 0..1: 32 d-cols

    int bh = blockIdx.y;
    int b = bh >> 4, h = bh & 15;
    int q0 = blockIdx.x * 128;
    const float* Pb = P + (size_t)bh * SEQ * SEQ + (size_t)q0 * SEQ;
    const __nv_bfloat16* VH = g_qkvH + (size_t)2 * NTOK * EMB + (size_t)(b * SEQ) * EMB + h * HDIM;
    const __nv_bfloat16* VL = g_qkvL + (size_t)2 * NTOK * EMB + (size_t)(b * SEQ) * EMB + h * HDIM;

    float acc[2][4][4];
#pragma unroll
    for (int i = 0; i < 2; i++)
#pragma unroll
        for (int j = 0; j < 4; j++)
#pragma unroll
            for (int q = 0; q < 4; q++) acc[i][j][q] = 0.0f;

    int lr = lane & 15;
    int lh = lane >> 4;
    uint32_t a_off = (uint32_t)((wm * 32 + lr) * PV_PROWB + lh * 16);
    // trans-ldmatrix V address: row = seq-k (lane&15 within 16-slice),
    // column byte = d (wn*32 + (lane>>4)*8 elements)
    uint32_t vb_off = (uint32_t)(lr * PV_VROWB + (wn * 32 + lh * 8) * 2);

    for (int kc = 0; kc < SEQ / 128; kc++) {
        if (kc) __syncthreads();       // previous chunk compute done
        // V chunk: 2 tiles x 128 rows x 8 chunks of 16B = 2048 cp.async
#pragma unroll
        for (int j = 0; j < 8; j++) {
            int q = j * 256 + t;       // 0..2047
            int op = q >> 10;          // 0: VH, 1: VL
            int r = (q >> 3) & 127;
            int c = q & 7;
            const __nv_bfloat16* src = (op ? VL : VH) + (size_t)(kc * 128 + r) * EMB + c * 8;
            uint32_t dst = sb + (op ? PV_VL : PV_VH) + r * PV_VROWB + c * 16;
            cp_async16(dst, src);
        }
        CP_COMMIT();
        // P chunk: 128 x 128 fp32 -> bf16 hi/lo in smem
#pragma unroll
        for (int j = 0; j < 16; j++) {
            int idx = j * 256 + t;     // 0..4095 float4s
            int r = idx >> 5;
            int c4 = idx & 31;
            float4 v = *(const float4*)(Pb + (size_t)r * SEQ + kc * 128 + c4 * 4);
            __nv_bfloat162 h01, l01, h23, l23;
            split_bf16(v.x, h01.x, l01.x);
            split_bf16(v.y, h01.y, l01.y);
            split_bf16(v.z, h23.x, l23.x);
            split_bf16(v.w, h23.y, l23.y);
            uint32_t off = (uint32_t)(r * PV_PROWB + c4 * 8);
            *(uint2*)(smem + PV_PH + off) = make_uint2(*(uint32_t*)&h01, *(uint32_t*)&h23);
            *(uint2*)(smem + PV_PL + off) = make_uint2(*(uint32_t*)&l01, *(uint32_t*)&l23);
        }
        CP_WAIT0();
        __syncthreads();

#pragma unroll
        for (int ks = 0; ks < 8; ks++) {           // 16 seq-k per step
            uint32_t koff = ks * 32;               // P column bytes
            uint32_t ph[2][4], pl[2][4];
#pragma unroll
            for (int mi = 0; mi < 2; mi++) {
                ldmatrix_x4(ph[mi][0], ph[mi][1], ph[mi][2], ph[mi][3],
                            sb + PV_PH + a_off + mi * 16 * PV_PROWB + koff);
                ldmatrix_x4(pl[mi][0], pl[mi][1], pl[mi][2], pl[mi][3],
                            sb + PV_PL + a_off + mi * 16 * PV_PROWB + koff);
            }
            uint32_t vrow = (uint32_t)(ks * 16 * PV_VROWB);
#pragma unroll
            for (int g = 0; g < 2; g++) {          // d groups of 16
                uint32_t vh[4], vl[4];
                ldmatrix_x4_trans(vh[0], vh[1], vh[2], vh[3],
                                  sb + PV_VH + vb_off + vrow + g * 32);
                ldmatrix_x4_trans(vl[0], vl[1], vl[2], vl[3],
                                  sb + PV_VL + vb_off + vrow + g * 32);
                uint32_t b0h[2] = {vh[0], vh[1]};   // n-subtile g*2
                uint32_t b1h[2] = {vh[2], vh[3]};   // n-subtile g*2+1
                uint32_t b0l[2] = {vl[0], vl[1]};
                uint32_t b1l[2] = {vl[2], vl[3]};
#pragma unroll
                for (int mi = 0; mi < 2; mi++) {
                    mma_16816(acc[mi][g * 2 + 0], ph[mi], b0h);
                    mma_16816(acc[mi][g * 2 + 1], ph[mi], b1h);
                    mma_16816(acc[mi][g * 2 + 0], ph[mi], b0l);
                    mma_16816(acc[mi][g * 2 + 1], ph[mi], b1l);
                    mma_16816(acc[mi][g * 2 + 0], pl[mi], b0h);
                    mma_16816(acc[mi][g * 2 + 1], pl[mi], b1h);
                }
            }
        }
    }

    float* Ob = O + (size_t)(b * SEQ) * EMB + h * HDIM;
#pragma unroll
    for (int mi = 0; mi < 2; mi++) {
        int r0 = q0 + wm * 32 + mi * 16 + (lane >> 2);
#pragma unroll
        for (int n = 0; n < 4; n++) {
            int col = wn * 32 + n * 8 + (lane & 3) * 2;
            *(float2*)(Ob + (size_t)r0 * EMB + col) =
                make_float2(acc[mi][n][0], acc[mi][n][1]);
            *(float2*)(Ob + (size_t)(r0 + 8) * EMB + col) =
                make_float2(acc[mi][n][2], acc[mi][n][3]);
        }
    }
}

// ---------------------------------------------------------------------------
extern "C" void kernel_launch(void* const* d_in, const int* in_sizes, int n_in,
                              void* d_out, int out_size) {
    (void)in_sizes; (void)n_in; (void)out_size;
    const float* X[3] = {(const float*)d_in[0], (const float*)d_in[1], (const float*)d_in[2]};
    float* out = (float*)d_out;                          // attn_output [B, L, E]
    float* attnw = out + (size_t)NTOK * EMB;             // attn_weights [B, H, L, L]

    cudaFuncSetAttribute(gemm_kan_mma, cudaFuncAttributeMaxDynamicSharedMemorySize, GEMM_SMEM);
    cudaFuncSetAttribute(qk_mma, cudaFuncAttributeMaxDynamicSharedMemorySize, QK_SMEM);
    cudaFuncSetAttribute(pv_mma, cudaFuncAttributeMaxDynamicSharedMemorySize, PV_SMEM);

    for (int p = 0; p < 3; p++) {
        phi_split_kernel<<<(NTOK * EMB) / 256, 256>>>(X[p]);
        wprep_split_kernel<<<(EMB * EMB) / 256, 256>>>((const float*)d_in[3 + 3 * p],
                                                       (const float*)d_in[4 + 3 * p],
                                                       (const float*)d_in[5 + 3 * p]);
        gemm_kan_mma<<<dim3(EMB / BN, NTOK / BM), 256, GEMM_SMEM>>>(p);
    }
    qk_mma<<<dim3(SEQ / 128, SEQ / 128, BATCH * HEADS), 256, QK_SMEM>>>(attnw);
    softmax_kernel<<<BATCH * HEADS * SEQ, 256>>>(attnw);
    pv_mma<<<dim3(SEQ / 128, BATCH * HEADS), 256, PV_SMEM>>>(attnw, out);
}

// round 9
// speedup vs baseline: 2.1464x; 1.0068x over previous
#include <cuda_runtime.h>
#include <cuda_bf16.h>
#include <cstdint>
#include <cstddef>

// Problem constants
#define BATCH 2
#define SEQ   2048
#define EMB   1024
#define HEADS 16
#define HDIM  64
#define NTOK  (BATCH * SEQ)          // 4096
#define KDIM  (EMB * 8)              // 8192 expanded features
#define NB    7                      // spline bases per feature

// ---------------- scratch (static device globals; no allocation) ------------
__device__ uint4 g_phiH4[(size_t)NTOK * KDIM / 8];   // 67 MB  bf16 hi
__device__ uint4 g_phiL4[(size_t)NTOK * KDIM / 8];   // 67 MB  bf16 lo
__device__ uint4 g_WH4[(size_t)EMB * KDIM / 8];      // 16 MB  (W stored [EMB, KDIM])
__device__ uint4 g_WL4[(size_t)EMB * KDIM / 8];      // 16 MB
// projected Q,K,V as bf16 hi/lo split, layout [3][NTOK][EMB]
__device__ __nv_bfloat16 g_qkvH[(size_t)3 * NTOK * EMB];  // 25 MB
__device__ __nv_bfloat16 g_qkvL[(size_t)3 * NTOK * EMB];  // 25 MB

// =====================  PTX helpers (compute_103-safe) ======================
__device__ __forceinline__ uint32_t smem_to_u32(const void* p) {
    uint32_t a;
    asm("{ .reg .u64 t; cvta.to.shared.u64 t, %1; cvt.u32.u64 %0, t; }" : "=r"(a) : "l"(p));
    return a;
}
__device__ __forceinline__ void cp_async16(uint32_t dst, const void* src) {
    asm volatile("cp.async.cg.shared.global [%0], [%1], 16;" :: "r"(dst), "l"(src));
}
#define CP_COMMIT() asm volatile("cp.async.commit_group;" ::: "memory")
#define CP_WAIT2()  asm volatile("cp.async.wait_group 2;" ::: "memory")
#define CP_WAIT0()  asm volatile("cp.async.wait_group 0;" ::: "memory")

__device__ __forceinline__ void ldmatrix_x4(uint32_t& r0, uint32_t& r1,
                                            uint32_t& r2, uint32_t& r3, uint32_t addr) {
    asm volatile("ldmatrix.sync.aligned.m8n8.x4.shared.b16 {%0,%1,%2,%3}, [%4];"
                 : "=r"(r0), "=r"(r1), "=r"(r2), "=r"(r3) : "r"(addr));
}
__device__ __forceinline__ void ldmatrix_x4_trans(uint32_t& r0, uint32_t& r1,
                                                  uint32_t& r2, uint32_t& r3, uint32_t addr) {
    asm volatile("ldmatrix.sync.aligned.m8n8.x4.trans.shared.b16 {%0,%1,%2,%3}, [%4];"
                 : "=r"(r0), "=r"(r1), "=r"(r2), "=r"(r3) : "r"(addr));
}
// D (fp32) += A(bf16, row) @ B(bf16, col) ; m16n8k16
__device__ __forceinline__ void mma_16816(float* d, const uint32_t* a, const uint32_t* b) {
    asm volatile(
        "mma.sync.aligned.m16n8k16.row.col.f32.bf16.bf16.f32 "
        "{%0,%1,%2,%3}, {%4,%5,%6,%7}, {%8,%9}, {%0,%1,%2,%3};"
        : "+f"(d[0]), "+f"(d[1]), "+f"(d[2]), "+f"(d[3])
        : "r"(a[0]), "r"(a[1]), "r"(a[2]), "r"(a[3]), "r"(b[0]), "r"(b[1]));
}
__device__ __forceinline__ void split_bf16(float v, __nv_bfloat16& h, __nv_bfloat16& l) {
    h = __float2bfloat16(v);
    l = __float2bfloat16(v - __bfloat162float(h));
}

// ---------------------------------------------------------------------------
// Kernel 1: expand X[NTOK, EMB] -> phi (x, B0..B6) bf16 hi/lo, [NTOK, KDIM]
// ---------------------------------------------------------------------------
__global__ __launch_bounds__(256) void phi_split_kernel(const float* __restrict__ X) {
    int idx = blockIdx.x * blockDim.x + threadIdx.x;
    if (idx >= NTOK * EMB) return;
    float x = X[idx];

    float b[10];
#pragma unroll
    for (int t = 0; t < 10; t++) {
        float gt = -2.5f + 0.5f * (float)t;
        b[t] = (x >= gt && x < gt + 0.5f) ? 1.0f : 0.0f;
    }
#pragma unroll
    for (int p = 1; p <= 3; p++) {
#pragma unroll
        for (int t = 0; t < 10; t++) {
            if (t + p < 10) {
                float gt   = -2.5f + 0.5f * (float)t;
                float gtp  = gt + 0.5f * (float)p;
                float gtp1 = gtp + 0.5f;
                float gt1  = gt + 0.5f;
                float left  = (x - gt)   / (gtp - gt);
                float right = (gtp1 - x) / (gtp1 - gt1);
                b[t] = left * b[t] + right * b[t + 1];
            }
        }
    }
    float v[8] = {x, b[0], b[1], b[2], b[3], b[4], b[5], b[6]};
    __nv_bfloat16 hi[8], lo[8];
#pragma unroll
    for (int j = 0; j < 8; j++) split_bf16(v[j], hi[j], lo[j]);
    g_phiH4[idx] = *(uint4*)hi;
    g_phiL4[idx] = *(uint4*)lo;
}

// ---------------------------------------------------------------------------
// Kernel 2: combined weight W[EMB(out m), KDIM] row-major, bf16 hi/lo
// ---------------------------------------------------------------------------
__global__ __launch_bounds__(256) void wprep_split_kernel(const float* __restrict__ base,
                                                          const float* __restrict__ spline,
                                                          const float* __restrict__ scaler) {
    int idx = blockIdx.x * blockDim.x + threadIdx.x;
    if (idx >= EMB * EMB) return;
    int i = idx & (EMB - 1);
    int m = idx >> 10;
    size_t mi = (size_t)m * EMB + i;
    float v[8];
    v[0] = base[mi];
    float sc = scaler[mi];
    const float* sp = spline + mi * NB;
#pragma unroll
    for (int j = 0; j < NB; j++) v[1 + j] = sp[j] * sc;

    __nv_bfloat16 hi[8], lo[8];
#pragma unroll
    for (int j = 0; j < 8; j++) split_bf16(v[j], hi[j], lo[j]);
    size_t o = (size_t)m * (KDIM / 8) + i;
    g_WH4[o] = *(uint4*)hi;
    g_WL4[o] = *(uint4*)lo;
}

// ---------------------------------------------------------------------------
// Kernel 3: mma.sync GEMM  C = phi @ W^T, 3-term bf16 split.
// CTA 128x256x32, 8 warps (2x4), warp tile 64x64, 3-stage cp.async.
// MMA issue in 3 term-passes to maximize accumulator reuse distance.
// ---------------------------------------------------------------------------
#define BM 128
#define BN 256
#define BK 32
#define NCH (KDIM / BK)                 // 256
#define ROWB 80
#define A_TILE (BM * ROWB)
#define B_TILE (BN * ROWB)
#define STAGE (2 * A_TILE + 2 * B_TILE)
#define OFF_AH 0
#define OFF_AL A_TILE
#define OFF_BH (2 * A_TILE)
#define OFF_BL (2 * A_TILE + B_TILE)
#define GEMM_SMEM (3 * STAGE)

__device__ __forceinline__ void load_stage(uint32_t sbase, int k0,
                                           const __nv_bfloat16* pAh, const __nv_bfloat16* pAl,
                                           const __nv_bfloat16* pBh, const __nv_bfloat16* pBl) {
    int t = threadIdx.x;
#pragma unroll
    for (int j = 0; j < 12; j++) {
        int q = j * 256 + t;
        const __nv_bfloat16* src;
        uint32_t dst;
        if (j < 2) {
            int lq = q;
            int r = lq >> 2, c = lq & 3;
            src = pAh + (size_t)r * KDIM + k0 + c * 8;
            dst = sbase + OFF_AH + r * ROWB + c * 16;
        } else if (j < 4) {
            int lq = q - 512;
            int r = lq >> 2, c = lq & 3;
            src = pAl + (size_t)r * KDIM + k0 + c * 8;
            dst = sbase + OFF_AL + r * ROWB + c * 16;
        } else if (j < 8) {
            int lq = q - 1024;
            int r = lq >> 2, c = lq & 3;
            src = pBh + (size_t)r * KDIM + k0 + c * 8;
            dst = sbase + OFF_BH + r * ROWB + c * 16;
        } else {
            int lq = q - 2048;
            int r = lq >> 2, c = lq & 3;
            src = pBl + (size_t)r * KDIM + k0 + c * 8;
            dst = sbase + OFF_BL + r * ROWB + c * 16;
        }
        cp_async16(dst, src);
    }
}

__global__ __launch_bounds__(256, 1) void gemm_kan_mma(int which) {
    extern __shared__ char smem[];
    uint32_t sb = smem_to_u32(smem);
    int t = threadIdx.x;
    int lane = t & 31;
    int w = t >> 5;
    int wm = w >> 2;
    int wn = w & 3;

    int row0 = blockIdx.y * BM;
    int col0 = blockIdx.x * BN;
    const __nv_bfloat16* pAh = (const __nv_bfloat16*)g_phiH4 + (size_t)row0 * KDIM;
    const __nv_bfloat16* pAl = (const __nv_bfloat16*)g_phiL4 + (size_t)row0 * KDIM;
    const __nv_bfloat16* pBh = (const __nv_bfloat16*)g_WH4 + (size_t)col0 * KDIM;
    const __nv_bfloat16* pBl = (const __nv_bfloat16*)g_WL4 + (size_t)col0 * KDIM;

    load_stage(sb + 0 * STAGE, 0 * BK, pAh, pAl, pBh, pBl); CP_COMMIT();
    load_stage(sb + 1 * STAGE, 1 * BK, pAh, pAl, pBh, pBl); CP_COMMIT();
    load_stage(sb + 2 * STAGE, 2 * BK, pAh, pAl, pBh, pBl); CP_COMMIT();

    float acc[4][8][4];
#pragma unroll
    for (int i = 0; i < 4; i++)
#pragma unroll
        for (int j = 0; j < 8; j++)
#pragma unroll
            for (int q = 0; q < 4; q++) acc[i][j][q] = 0.0f;

    int lr = lane & 15;
    int lh = lane >> 4;
    uint32_t a_off = (uint32_t)((wm * 64 + lr) * ROWB + lh * 16);
    uint32_t b_off = (uint32_t)((wn * 64 + lr) * ROWB + lh * 16);

    for (int c = 0; c < NCH; c++) {
        int buf = c - (c / 3) * 3;
        uint32_t st = sb + buf * STAGE;
        CP_WAIT2();
        __syncthreads();

#pragma unroll
        for (int ks = 0; ks < 2; ks++) {
            uint32_t koff = ks * 32;
            uint32_t ah[4][4], al[4][4];
#pragma unroll
            for (int i = 0; i < 4; i++) {
                ldmatrix_x4(ah[i][0], ah[i][1], ah[i][2], ah[i][3],
                            st + OFF_AH + a_off + i * 16 * ROWB + koff);
                ldmatrix_x4(al[i][0], al[i][1], al[i][2], al[i][3],
                            st + OFF_AL + a_off + i * 16 * ROWB + koff);
            }
            uint32_t bh[4][4], bl[4][4];
#pragma unroll
            for (int p = 0; p < 4; p++) {
                ldmatrix_x4(bh[p][0], bh[p][1], bh[p][2], bh[p][3],
                            st + OFF_BH + b_off + p * 16 * ROWB + koff);
                ldmatrix_x4(bl[p][0], bl[p][1], bl[p][2], bl[p][3],
                            st + OFF_BL + b_off + p * 16 * ROWB + koff);
            }
            // term pass 1: Ah * Bh  (all 32 accumulator quads, no RAW inside pass)
#pragma unroll
            for (int i = 0; i < 4; i++)
#pragma unroll
                for (int p = 0; p < 4; p++) {
                    uint32_t b0h[2] = {bh[p][0], bh[p][2]};
                    uint32_t b1h[2] = {bh[p][1], bh[p][3]};
                    mma_16816(acc[i][p * 2 + 0], ah[i], b0h);
                    mma_16816(acc[i][p * 2 + 1], ah[i], b1h);
                }
            // term pass 2: Ah * Bl
#pragma unroll
            for (int i = 0; i < 4; i++)
#pragma unroll
                for (int p = 0; p < 4; p++) {
                    uint32_t b0l[2] = {bl[p][0], bl[p][2]};
                    uint32_t b1l[2] = {bl[p][1], bl[p][3]};
                    mma_16816(acc[i][p * 2 + 0], ah[i], b0l);
                    mma_16816(acc[i][p * 2 + 1], ah[i], b1l);
                }
            // term pass 3: Al * Bh
#pragma unroll
            for (int i = 0; i < 4; i++)
#pragma unroll
                for (int p = 0; p < 4; p++) {
                    uint32_t b0h[2] = {bh[p][0], bh[p][2]};
                    uint32_t b1h[2] = {bh[p][1], bh[p][3]};
                    mma_16816(acc[i][p * 2 + 0], al[i], b0h);
                    mma_16816(acc[i][p * 2 + 1], al[i], b1h);
                }
        }
        __syncthreads();
        if (c + 3 < NCH) load_stage(st, (c + 3) * BK, pAh, pAl, pBh, pBl);
        CP_COMMIT();
    }

    // epilogue: split fp32 accumulators to bf16 hi/lo and store
    __nv_bfloat16* CH = g_qkvH + (size_t)which * NTOK * EMB;
    __nv_bfloat16* CL = g_qkvL + (size_t)which * NTOK * EMB;
    int mbase = row0 + wm * 64 + (lane >> 2);
    int nbase = col0 + wn * 64 + (lane & 3) * 2;
#pragma unroll
    for (int i = 0; i < 4; i++) {
#pragma unroll
        for (int j = 0; j < 8; j++) {
            size_t o0 = (size_t)(mbase + i * 16) * EMB + nbase + j * 8;
            size_t o1 = o0 + (size_t)8 * EMB;
            __nv_bfloat162 h2, l2;
            split_bf16(acc[i][j][0], h2.x, l2.x);
            split_bf16(acc[i][j][1], h2.y, l2.y);
            *(uint32_t*)(CH + o0) = *(uint32_t*)&h2;
            *(uint32_t*)(CL + o0) = *(uint32_t*)&l2;
            split_bf16(acc[i][j][2], h2.x, l2.x);
            split_bf16(acc[i][j][3], h2.y, l2.y);
            *(uint32_t*)(CH + o1) = *(uint32_t*)&h2;
            *(uint32_t*)(CL + o1) = *(uint32_t*)&l2;
        }
    }
}

// ---------------------------------------------------------------------------
// Kernel 4: scores via mma, 3-term split. CTA = (bh, 128q, 128k), one-shot.
// ---------------------------------------------------------------------------
#define QK_ROWB 144
#define QK_TILE (128 * QK_ROWB)          // 18432
#define QK_QH 0
#define QK_QL QK_TILE
#define QK_KH (2 * QK_TILE)
#define QK_KL (3 * QK_TILE)
#define QK_SMEM (4 * QK_TILE)            // 73728

__global__ __launch_bounds__(256, 2) void qk_mma(float* __restrict__ S) {
    extern __shared__ char smem[];
    uint32_t sb = smem_to_u32(smem);
    int t = threadIdx.x;
    int lane = t & 31;
    int w = t >> 5;
    int wm = w >> 1;          // 0..3: 32 q-rows each
    int wn = w & 1;           // 0..1: 64 k-cols each

    int bh = blockIdx.z;
    int b = bh >> 4, h = bh & 15;
    int q0 = blockIdx.y * 128;
    int k0 = blockIdx.x * 128;

    const __nv_bfloat16* QH = g_qkvH + ((size_t)(b * SEQ + q0)) * EMB + h * HDIM;
    const __nv_bfloat16* QL = g_qkvL + ((size_t)(b * SEQ + q0)) * EMB + h * HDIM;
    const __nv_bfloat16* KH = g_qkvH + (size_t)NTOK * EMB + ((size_t)(b * SEQ + k0)) * EMB + h * HDIM;
    const __nv_bfloat16* KL = g_qkvL + (size_t)NTOK * EMB + ((size_t)(b * SEQ + k0)) * EMB + h * HDIM;

    {
        const __nv_bfloat16* srcs[4] = {QH, QL, KH, KL};
        uint32_t dsts[4] = {sb + QK_QH, sb + QK_QL, sb + QK_KH, sb + QK_KL};
#pragma unroll
        for (int j = 0; j < 16; j++) {
            int q = j * 256 + t;          // 0..4095
            int op = q >> 10;
            int r = (q >> 3) & 127;
            int c = q & 7;
            cp_async16(dsts[op] + r * QK_ROWB + c * 16,
                       srcs[op] + (size_t)r * EMB + c * 8);
        }
    }
    CP_COMMIT();
    CP_WAIT0();
    __syncthreads();

    float acc[2][8][4];
#pragma unroll
    for (int i = 0; i < 2; i++)
#pragma unroll
        for (int j = 0; j < 8; j++)
#pragma unroll
            for (int q = 0; q < 4; q++) acc[i][j][q] = 0.0f;

    int lr = lane & 15;
    int lh = lane >> 4;
    uint32_t a_off = (uint32_t)((wm * 32 + lr) * QK_ROWB + lh * 16);
    uint32_t b_off = (uint32_t)((wn * 64 + lr) * QK_ROWB + lh * 16);

#pragma unroll
    for (int ks = 0; ks < 4; ks++) {
        uint32_t koff = ks * 32;
        uint32_t ah[2][4], al[2][4];
#pragma unroll
        for (int mi = 0; mi < 2; mi++) {
            ldmatrix_x4(ah[mi][0], ah[mi][1], ah[mi][2], ah[mi][3],
                        sb + QK_QH + a_off + mi * 16 * QK_ROWB + koff);
            ldmatrix_x4(al[mi][0], al[mi][1], al[mi][2], al[mi][3],
                        sb + QK_QL + a_off + mi * 16 * QK_ROWB + koff);
        }
#pragma unroll
        for (int p = 0; p < 4; p++) {
            uint32_t kh[4], kl[4];
            ldmatrix_x4(kh[0], kh[1], kh[2], kh[3],
                        sb + QK_KH + b_off + p * 16 * QK_ROWB + koff);
            ldmatrix_x4(kl[0], kl[1], kl[2], kl[3],
                        sb + QK_KL + b_off + p * 16 * QK_ROWB + koff);
            uint32_t b0h[2] = {kh[0], kh[2]};
            uint32_t b1h[2] = {kh[1], kh[3]};
            uint32_t b0l[2] = {kl[0], kl[2]};
            uint32_t b1l[2] = {kl[1], kl[3]};
            // term passes: 4 accumulator quads per pass (dist 4)
#pragma unroll
            for (int mi = 0; mi < 2; mi++) {
                mma_16816(acc[mi][p * 2 + 0], ah[mi], b0h);
                mma_16816(acc[mi][p * 2 + 1], ah[mi], b1h);
            }
#pragma unroll
            for (int mi = 0; mi < 2; mi++) {
                mma_16816(acc[mi][p * 2 + 0], ah[mi], b0l);
                mma_16816(acc[mi][p * 2 + 1], ah[mi], b1l);
            }
#pragma unroll
            for (int mi = 0; mi < 2; mi++) {
                mma_16816(acc[mi][p * 2 + 0], al[mi], b0h);
                mma_16816(acc[mi][p * 2 + 1], al[mi], b1h);
            }
        }
    }

    float* Sb = S + (size_t)bh * SEQ * SEQ;
    const float scale = 0.125f;
#pragma unroll
    for (int mi = 0; mi < 2; mi++) {
        int r0 = q0 + wm * 32 + mi * 16 + (lane >> 2);
#pragma unroll
        for (int n = 0; n < 8; n++) {
            int col = k0 + wn * 64 + n * 8 + (lane & 3) * 2;
            *(float2*)(Sb + (size_t)r0 * SEQ + col) =
                make_float2(acc[mi][n][0] * scale, acc[mi][n][1] * scale);
            *(float2*)(Sb + (size_t)(r0 + 8) * SEQ + col) =
                make_float2(acc[mi][n][2] * scale, acc[mi][n][3] * scale);
        }
    }
}

// ---------------------------------------------------------------------------
// Kernel 5: in-place row softmax (one CTA per row of length SEQ)
// ---------------------------------------------------------------------------
__global__ __launch_bounds__(256) void softmax_kernel(float* __restrict__ W) {
    float* p = W + (size_t)blockIdx.x * SEQ;
    int t = threadIdx.x;
    float4 a = ((float4*)p)[t];
    float4 b = ((float4*)p)[t + 256];

    float m = fmaxf(fmaxf(fmaxf(a.x, a.y), fmaxf(a.z, a.w)),
                    fmaxf(fmaxf(b.x, b.y), fmaxf(b.z, b.w)));
#pragma unroll
    for (int o = 16; o > 0; o >>= 1) m = fmaxf(m, __shfl_xor_sync(0xffffffffu, m, o));

    __shared__ float red_max[8];
    __shared__ float red_sum[8];
    if ((t & 31) == 0) red_max[t >> 5] = m;
    __syncthreads();
    if (t < 32) {
        float v = (t < 8) ? red_max[t] : -3.402823466e38f;
#pragma unroll
        for (int o = 4; o > 0; o >>= 1) v = fmaxf(v, __shfl_xor_sync(0xffffffffu, v, o));
        if (t == 0) red_max[0] = v;
    }
    __syncthreads();
    m = red_max[0];

    a.x = __expf(a.x - m); a.y = __expf(a.y - m); a.z = __expf(a.z - m); a.w = __expf(a.w - m);
    b.x = __expf(b.x - m); b.y = __expf(b.y - m); b.z = __expf(b.z - m); b.w = __expf(b.w - m);
    float s = a.x + a.y + a.z + a.w + b.x + b.y + b.z + b.w;
#pragma unroll
    for (int o = 16; o > 0; o >>= 1) s += __shfl_xor_sync(0xffffffffu, s, o);
    if ((t & 31) == 0) red_sum[t >> 5] = s;
    __syncthreads();
    if (t < 32) {
        float v = (t < 8) ? red_sum[t] : 0.0f;
#pragma unroll
        for (int o = 4; o > 0; o >>= 1) v += __shfl_xor_sync(0xffffffffu, v, o);
        if (t == 0) red_sum[0] = v;
    }
    __syncthreads();
    float inv = 1.0f / red_sum[0];

    a.x *= inv; a.y *= inv; a.z *= inv; a.w *= inv;
    b.x *= inv; b.y *= inv; b.z *= inv; b.w *= inv;
    ((float4*)p)[t] = a;
    ((float4*)p)[t + 256] = b;
}

// ---------------------------------------------------------------------------
// Kernel 6: O = P @ V via mma, 3-term split (PhVh + PhVl + PlVh).
// V k-major in smem, consumed with ldmatrix.x4.trans; 3 term-passes (dist 8).
// ---------------------------------------------------------------------------
#define PV_PROWB 272                     // 128 bf16 + 16B pad
#define PV_VROWB 144
#define PV_PH 0
#define PV_PL (128 * PV_PROWB)                       // 34816
#define PV_VH (2 * 128 * PV_PROWB)                   // 69632
#define PV_VL (2 * 128 * PV_PROWB + 128 * PV_VROWB)  // 88064
#define PV_SMEM (2 * 128 * PV_PROWB + 2 * 128 * PV_VROWB)  // 106496

__global__ __launch_bounds__(256, 2) void pv_mma(const float* __restrict__ P,
                                                 float* __restrict__ O) {
    extern __shared__ char smem[];
    uint32_t sb = smem_to_u32(smem);
    int t = threadIdx.x;
    int lane = t & 31;
    int w = t >> 5;
    int wm = w >> 1;          // 0..3: 32 q-rows
    int wn = w & 1;           // 0..1: 32 d-cols

    int bh = blockIdx.y;
    int b = bh >> 4, h = bh & 15;
    int q0 = blockIdx.x * 128;
    const float* Pb = P + (size_t)bh * SEQ * SEQ + (size_t)q0 * SEQ;
    const __nv_bfloat16* VH = g_qkvH + (size_t)2 * NTOK * EMB + (size_t)(b * SEQ) * EMB + h * HDIM;
    const __nv_bfloat16* VL = g_qkvL + (size_t)2 * NTOK * EMB + (size_t)(b * SEQ) * EMB + h * HDIM;

    float acc[2][4][4];
#pragma unroll
    for (int i = 0; i < 2; i++)
#pragma unroll
        for (int j = 0; j < 4; j++)
#pragma unroll
            for (int q = 0; q < 4; q++) acc[i][j][q] = 0.0f;

    int lr = lane & 15;
    int lh = lane >> 4;
    uint32_t a_off = (uint32_t)((wm * 32 + lr) * PV_PROWB + lh * 16);
    uint32_t vb_off = (uint32_t)(lr * PV_VROWB + (wn * 32 + lh * 8) * 2);

    for (int kc = 0; kc < SEQ / 128; kc++) {
        if (kc) __syncthreads();
#pragma unroll
        for (int j = 0; j < 8; j++) {
            int q = j * 256 + t;       // 0..2047
            int op = q >> 10;
            int r = (q >> 3) & 127;
            int c = q & 7;
            const __nv_bfloat16* src = (op ? VL : VH) + (size_t)(kc * 128 + r) * EMB + c * 8;
            uint32_t dst = sb + (op ? PV_VL : PV_VH) + r * PV_VROWB + c * 16;
            cp_async16(dst, src);
        }
        CP_COMMIT();
#pragma unroll
        for (int j = 0; j < 16; j++) {
            int idx = j * 256 + t;
            int r = idx >> 5;
            int c4 = idx & 31;
            float4 v = *(const float4*)(Pb + (size_t)r * SEQ + kc * 128 + c4 * 4);
            __nv_bfloat162 h01, l01, h23, l23;
            split_bf16(v.x, h01.x, l01.x);
            split_bf16(v.y, h01.y, l01.y);
            split_bf16(v.z, h23.x, l23.x);
            split_bf16(v.w, h23.y, l23.y);
            uint32_t off = (uint32_t)(r * PV_PROWB + c4 * 8);
            *(uint2*)(smem + PV_PH + off) = make_uint2(*(uint32_t*)&h01, *(uint32_t*)&h23);
            *(uint2*)(smem + PV_PL + off) = make_uint2(*(uint32_t*)&l01, *(uint32_t*)&l23);
        }
        CP_WAIT0();
        __syncthreads();

#pragma unroll
        for (int ks = 0; ks < 8; ks++) {
            uint32_t koff = ks * 32;
            uint32_t ph[2][4], pl[2][4];
#pragma unroll
            for (int mi = 0; mi < 2; mi++) {
                ldmatrix_x4(ph[mi][0], ph[mi][1], ph[mi][2], ph[mi][3],
                            sb + PV_PH + a_off + mi * 16 * PV_PROWB + koff);
                ldmatrix_x4(pl[mi][0], pl[mi][1], pl[mi][2], pl[mi][3],
                            sb + PV_PL + a_off + mi * 16 * PV_PROWB + koff);
            }
            uint32_t vrow = (uint32_t)(ks * 16 * PV_VROWB);
            uint32_t vh[2][4], vl[2][4];
#pragma unroll
            for (int g = 0; g < 2; g++) {
                ldmatrix_x4_trans(vh[g][0], vh[g][1], vh[g][2], vh[g][3],
                                  sb + PV_VH + vb_off + vrow + g * 32);
                ldmatrix_x4_trans(vl[g][0], vl[g][1], vl[g][2], vl[g][3],
                                  sb + PV_VL + vb_off + vrow + g * 32);
            }
            // term pass 1: Ph*Vh over all 8 quads
#pragma unroll
            for (int mi = 0; mi < 2; mi++)
#pragma unroll
                for (int g = 0; g < 2; g++) {
                    uint32_t b0[2] = {vh[g][0], vh[g][1]};
                    uint32_t b1[2] = {vh[g][2], vh[g][3]};
                    mma_16816(acc[mi][g * 2 + 0], ph[mi], b0);
                    mma_16816(acc[mi][g * 2 + 1], ph[mi], b1);
                }
            // term pass 2: Ph*Vl
#pragma unroll
            for (int mi = 0; mi < 2; mi++)
#pragma unroll
                for (int g = 0; g < 2; g++) {
                    uint32_t b0[2] = {vl[g][0], vl[g][1]};
                    uint32_t b1[2] = {vl[g][2], vl[g][3]};
                    mma_16816(acc[mi][g * 2 + 0], ph[mi], b0);
                    mma_16816(acc[mi][g * 2 + 1], ph[mi], b1);
                }
            // term pass 3: Pl*Vh
#pragma unroll
            for (int mi = 0; mi < 2; mi++)
#pragma unroll
                for (int g = 0; g < 2; g++) {
                    uint32_t b0[2] = {vh[g][0], vh[g][1]};
                    uint32_t b1[2] = {vh[g][2], vh[g][3]};
                    mma_16816(acc[mi][g * 2 + 0], pl[mi], b0);
                    mma_16816(acc[mi][g * 2 + 1], pl[mi], b1);
                }
        }
    }

    float* Ob = O + (size_t)(b * SEQ) * EMB + h * HDIM;
#pragma unroll
    for (int mi = 0; mi < 2; mi++) {
        int r0 = q0 + wm * 32 + mi * 16 + (lane >> 2);
#pragma unroll
        for (int n = 0; n < 4; n++) {
            int col = wn * 32 + n * 8 + (lane & 3) * 2;
            *(float2*)(Ob + (size_t)r0 * EMB + col) =
                make_float2(acc[mi][n][0], acc[mi][n][1]);
            *(float2*)(Ob + (size_t)(r0 + 8) * EMB + col) =
                make_float2(acc[mi][n][2], acc[mi][n][3]);
        }
    }
}

// ---------------------------------------------------------------------------
extern "C" void kernel_launch(void* const* d_in, const int* in_sizes, int n_in,
                              void* d_out, int out_size) {
    (void)in_sizes; (void)n_in; (void)out_size;
    const float* X[3] = {(const float*)d_in[0], (const float*)d_in[1], (const float*)d_in[2]};
    float* out = (float*)d_out;                          // attn_output [B, L, E]
    float* attnw = out + (size_t)NTOK * EMB;             // attn_weights [B, H, L, L]

    cudaFuncSetAttribute(gemm_kan_mma, cudaFuncAttributeMaxDynamicSharedMemorySize, GEMM_SMEM);
    cudaFuncSetAttribute(qk_mma, cudaFuncAttributeMaxDynamicSharedMemorySize, QK_SMEM);
    cudaFuncSetAttribute(pv_mma, cudaFuncAttributeMaxDynamicSharedMemorySize, PV_SMEM);

    for (int p = 0; p < 3; p++) {
        phi_split_kernel<<<(NTOK * EMB) / 256, 256>>>(X[p]);
        wprep_split_kernel<<<(EMB * EMB) / 256, 256>>>((const float*)d_in[3 + 3 * p],
                                                       (const float*)d_in[4 + 3 * p],
                                                       (const float*)d_in[5 + 3 * p]);
        gemm_kan_mma<<<dim3(EMB / BN, NTOK / BM), 256, GEMM_SMEM>>>(p);
    }
    qk_mma<<<dim3(SEQ / 128, SEQ / 128, BATCH * HEADS), 256, QK_SMEM>>>(attnw);
    softmax_kernel<<<BATCH * HEADS * SEQ, 256>>>(attnw);
    pv_mma<<<dim3(SEQ / 128, BATCH * HEADS), 256, PV_SMEM>>>(attnw, out);
}